// round 8
// baseline (speedup 1.0000x reference)
#include <cuda_runtime.h>
#include <math.h>
#include <stdint.h>

#define N_NODES 50000
#define E_EDGES 200000
#define TOT_E   250000
#define HID     64
#define XD      512

// ---------------- device scratch --------------------------------------------
__device__ int   g_cnt[N_NODES + 1];
__device__ int   g_cur[N_NODES];
__device__ int   g_srcs[TOT_E];       // CSR entries as COMPACT src indices
__device__ int   g_order[N_NODES];    // compact slot -> node id (mask desc)
__device__ int   g_inv[N_NODES];      // node id -> compact slot
__device__ int   g_histp[196][4];     // per-block mask histograms
__device__ int   g_nact[4];
__device__ float g_h0[N_NODES * HID];
__device__ float g_h[N_NODES * HID];
__device__ float g_xlr[(size_t)(N_NODES + 128) * XD];   // compact-indexed
__device__ float g_Wp[128 * XD];      // [Wl|Wr] rows, tf32-truncated (t>0)
__device__ float g_Wsum[64 * XD];     // Wc1+Wc2 truncated (t=0, K=64)
__device__ float g_biasC[XD];
__device__ float g_bias2[HID];

__device__ __forceinline__ float t32(float v) {
    uint32_t u; asm("cvt.rna.tf32.f32 %0, %1;" : "=r"(u) : "f"(v));
    return __uint_as_float(u);
}

// ---------------- L0: fused h0 / weight-prep / Wsum / cnt-init+hist ----------
#define L0_H0   12500
#define L0_PB   (L0_H0 + 256)
#define L0_WS   (L0_PB + 128)
#define L0_GRID (L0_WS + 196)

__global__ void k_l0(const float* __restrict__ feat, const float* __restrict__ W_in,
                     const float* __restrict__ b_in,
                     const float* __restrict__ Wl, const float* __restrict__ Wr,
                     const float* __restrict__ bl, const float* __restrict__ br,
                     const float* __restrict__ bconv, const int* __restrict__ mask) {
    __shared__ float Ws[32 * 64];
    __shared__ float fs[4][32];
    __shared__ int sh[4];
    int b = blockIdx.x, tid = threadIdx.x;
    if (b < L0_H0) {
        for (int i = tid; i < 32 * 64; i += 256) Ws[i] = W_in[i];
        if (tid < 128) {
            int r = b * 4 + (tid >> 5);
            fs[tid >> 5][tid & 31] = (r < N_NODES) ? feat[r * 32 + (tid & 31)] : 0.f;
        }
        __syncthreads();
        int ty = tid >> 6, c = tid & 63;
        int r = b * 4 + ty;
        if (r >= N_NODES) return;
        float s = b_in[c];
#pragma unroll
        for (int k = 0; k < 32; k++) s += fs[ty][k] * Ws[k * 64 + c];
        float sv = t32(s);
        g_h0[r * 64 + c] = sv;
        g_h[r * 64 + c] = sv;
    } else if (b < L0_PB) {
        int idx = (b - L0_H0) * 256 + tid;
        int k = idx >> 9, j = idx & 511;
        float v = (j < 256) ? Wl[k * 256 + j] : Wr[k * 256 + (j - 256)];
        g_Wp[idx] = t32(v);
        if (idx < XD) g_biasC[idx] = (idx < 256) ? bl[idx] : br[idx - 256];
        if (idx < HID)
            g_bias2[idx] = bconv[idx] + bconv[64 + idx] + bconv[128 + idx] + bconv[192 + idx];
    } else if (b < L0_WS) {
        int idx = (b - L0_PB) * 256 + tid;
        int k = idx >> 9, j = idx & 511;
        float v;
        if (j < 256) v = Wl[k * 256 + j] + Wl[(k + 64) * 256 + j];
        else         v = Wr[k * 256 + (j - 256)] + Wr[(k + 64) * 256 + (j - 256)];
        g_Wsum[idx] = t32(v);
    } else {
        int hb = b - L0_WS;
        if (tid < 4) sh[tid] = 0;
        __syncthreads();
        int i = hb * 256 + tid;
        if (i < N_NODES) {
            g_cnt[i] = 1;
            int m = mask[i]; m = m < 0 ? 0 : (m > 3 ? 3 : m);
            atomicAdd(&sh[m], 1);
        }
        __syncthreads();
        if (tid < 4) g_histp[hb][tid] = sh[tid];
    }
}

// ---------------- count incoming edges ---------------------------------------
__global__ void k_count(const int* __restrict__ ei) {
    int e = blockIdx.x * blockDim.x + threadIdx.x;
    if (e < E_EDGES) atomicAdd(&g_cnt[ei[E_EDGES + e]], 1);
}

// ---------------- fused scan + bucket scatter (1 block) ----------------------
__global__ void k_scansc(const int* __restrict__ mask) {
    __shared__ int wsum[32];
    __shared__ int cur4[4];
    int tid = threadIdx.x, lane = tid & 31, wid = tid >> 5;
    if (tid < 4) cur4[tid] = 0;
    __syncthreads();
    if (tid < 784) atomicAdd(&cur4[tid & 3], g_histp[tid >> 2][tid & 3]);
    __syncthreads();
    if (tid == 0) {
        int h1 = cur4[1], h2 = cur4[2], h3 = cur4[3];
        cur4[3] = 0; cur4[2] = h3; cur4[1] = h3 + h2; cur4[0] = h3 + h2 + h1;
        g_nact[0] = h3 + h2 + h1; g_nact[1] = h3 + h2; g_nact[2] = h3; g_nact[3] = 0;
    }
    __syncthreads();
    int carry = 0;
    for (int base = 0; base < N_NODES; base += 1024) {
        int i = base + tid;
        bool act = (i < N_NODES);
        int v = act ? g_cnt[i] : 0;
        int sv = v;
#pragma unroll
        for (int d = 1; d < 32; d <<= 1) {
            int u = __shfl_up_sync(0xffffffffu, sv, d);
            if (lane >= d) sv += u;
        }
        if (lane == 31) wsum[wid] = sv;
        __syncthreads();
        if (wid == 0) {
            int w = wsum[lane];
#pragma unroll
            for (int d = 1; d < 32; d <<= 1) {
                int u = __shfl_up_sync(0xffffffffu, w, d);
                if (lane >= d) w += u;
            }
            wsum[lane] = w;
        }
        __syncthreads();
        int add = (wid > 0) ? wsum[wid - 1] : 0;
        int incl = sv + add + carry;
        int beg = incl - v;
        int m = 0;
        if (act) { m = mask[i]; m = m < 0 ? 0 : (m > 3 ? 3 : m); }
        unsigned b0 = __ballot_sync(0xffffffffu, act && m == 0);
        unsigned b1 = __ballot_sync(0xffffffffu, act && m == 1);
        unsigned b2 = __ballot_sync(0xffffffffu, act && m == 2);
        unsigned b3 = __ballot_sync(0xffffffffu, act && m == 3);
        unsigned mym = (m == 0) ? b0 : (m == 1) ? b1 : (m == 2) ? b2 : b3;
        if (!act) mym = 1u;
        int rank = __popc(mym & ((1u << lane) - 1));
        int leader = __ffs(mym) - 1;
        int basep = 0;
        if (act && lane == leader) basep = atomicAdd(&cur4[m], __popc(mym));
        basep = __shfl_sync(0xffffffffu, basep, leader);
        if (act) {
            int pos = basep + rank;
            g_order[pos] = i;
            g_inv[i] = pos;
            g_cnt[i] = incl;
            g_srcs[beg] = pos;
            g_cur[i] = beg + 1;
        }
        int total = wsum[31];
        __syncthreads();
        carry += total;
    }
}

// ---------------- fill CSR with compact src ids ------------------------------
__global__ void k_fill(const int* __restrict__ ei) {
    int e = blockIdx.x * blockDim.x + threadIdx.x;
    if (e >= E_EDGES) return;
    int d = ei[E_EDGES + e];
    int p = atomicAdd(&g_cur[d], 1);
    g_srcs[p] = g_inv[ei[e]];
}

// ---------------- HMMA tf32 GEMM v3: tile 128x64, 2 CTAs/SM ------------------
// xlr[compact,512] = A @ W + biasC;  A = [h|h0] (K=128) or h (K=64 vs Wsum).
// XOR-swizzled smem (no pad): colA ^= (m&7)<<2, colB ^= (k&3)<<3.
// 8 warps = 4M x 2N, warp tile 32x32 (mf=2, nf=4).
#define GEMM_SMEM (96 * 1024)

template<int KD>
__device__ __forceinline__ void gemm_body(int tsel, uint32_t* smg) {
    uint32_t* As = smg;                 // [128][KD] swizzled
    uint32_t* Bs = smg + 16384;         // [KD][64] swizzled (fixed 64KB offset)
    int nact = g_nact[tsel];
    int ntile = (nact + 127) >> 7;
    int colB = blockIdx.x * 64;
    int tid = threadIdx.x, lane = tid & 31, wid = tid >> 5;
    int mwarp = wid >> 1, nwarp = wid & 1;
    int g = lane >> 2, t = lane & 3;
    const float* W = (KD == 128) ? g_Wp : g_Wsum;

    // ---- B stage once per CTA: Bs[k][n^((k&3)<<3)] --------------------------
    for (int i = tid; i < KD * 16; i += 256) {
        int k = i >> 4, n4 = (i & 15) * 4;
        float4 v = *(const float4*)&W[k * 512 + colB + n4];
        int cp = n4 ^ ((k & 3) << 3);
        uint32_t* d = &Bs[k * 64 + cp];
        d[0] = __float_as_uint(v.x); d[1] = __float_as_uint(v.y);
        d[2] = __float_as_uint(v.z); d[3] = __float_as_uint(v.w);
    }

    float2 bia[4];
#pragma unroll
    for (int nf = 0; nf < 4; nf++)
        bia[nf] = *(const float2*)&g_biasC[colB + nwarp * 32 + nf * 8 + 2 * t];

    int m_st = tid >> 1, half = tid & 1;
    int sw_st = (m_st & 7) << 2;

    for (int tile = blockIdx.y; tile < ntile; tile += gridDim.y) {
        int row0 = tile << 7;
        __syncthreads();                      // prev tile reads done; B ready
        // ---- A stage: row m = [h | h0] (K=128) or h (K=64) -----------------
        {
            int r = row0 + m_st;
            int gr = (r < nact) ? g_order[r] : g_order[0];
            const float* src;
            int kbase, ncpy;
            if (KD == 128) { src = half ? g_h0 : g_h; kbase = half * 64; ncpy = 16; }
            else           { src = g_h;              kbase = half * 32; ncpy = 8; }
            const float4* sp = (const float4*)&src[(size_t)gr * 64 + (KD == 128 ? 0 : kbase)];
#pragma unroll
            for (int i = 0; i < ncpy; i++) {
                float4 v = sp[i];
                int cp = (kbase + i * 4) ^ sw_st;
                uint32_t* d = &As[m_st * KD + cp];
                d[0] = __float_as_uint(v.x); d[1] = __float_as_uint(v.y);
                d[2] = __float_as_uint(v.z); d[3] = __float_as_uint(v.w);
            }
        }
        __syncthreads();

        // ---- mainloop -------------------------------------------------------
        float acc[2][4][4];
#pragma unroll
        for (int mf = 0; mf < 2; mf++)
#pragma unroll
            for (int nf = 0; nf < 4; nf++)
#pragma unroll
                for (int q = 0; q < 4; q++) acc[mf][nf][q] = 0.f;

        int aRow = mwarp * 32 + g;
        int bCol = nwarp * 32 + g;
#pragma unroll
        for (int k0 = 0; k0 < KD / 8; k0++) {
            int kk = k0 * 8 + t;
            uint32_t a[2][4], b[4][2];
            int ca = kk ^ (g << 2);
            int ca2 = ca ^ 4;
#pragma unroll
            for (int mf = 0; mf < 2; mf++) {
                const uint32_t* ap = &As[(aRow + mf * 16) * KD];
                a[mf][0] = ap[ca];
                a[mf][1] = ap[8 * KD + ca];
                a[mf][2] = ap[ca2];
                a[mf][3] = ap[8 * KD + ca2];
            }
#pragma unroll
            for (int nf = 0; nf < 4; nf++) {
                int cb = (bCol + nf * 8) ^ (t << 3);
                b[nf][0] = Bs[kk * 64 + cb];
                b[nf][1] = Bs[(kk + 4) * 64 + cb];
            }
#pragma unroll
            for (int mf = 0; mf < 2; mf++)
#pragma unroll
                for (int nf = 0; nf < 4; nf++) {
                    asm volatile(
                        "mma.sync.aligned.m16n8k8.row.col.f32.tf32.tf32.f32 "
                        "{%0,%1,%2,%3}, {%4,%5,%6,%7}, {%8,%9}, {%0,%1,%2,%3};"
                        : "+f"(acc[mf][nf][0]), "+f"(acc[mf][nf][1]),
                          "+f"(acc[mf][nf][2]), "+f"(acc[mf][nf][3])
                        : "r"(a[mf][0]), "r"(a[mf][1]), "r"(a[mf][2]), "r"(a[mf][3]),
                          "r"(b[nf][0]), "r"(b[nf][1]));
                }
        }

        // ---- epilogue -------------------------------------------------------
#pragma unroll
        for (int mf = 0; mf < 2; mf++) {
            int r0 = row0 + mwarp * 32 + mf * 16 + g;
#pragma unroll
            for (int nf = 0; nf < 4; nf++) {
                int c = colB + nwarp * 32 + nf * 8 + 2 * t;
                if (r0 < nact) {
                    float2 v = make_float2(acc[mf][nf][0] + bia[nf].x,
                                           acc[mf][nf][1] + bia[nf].y);
                    *(float2*)&g_xlr[(size_t)r0 * XD + c] = v;
                }
                if (r0 + 8 < nact) {
                    float2 v = make_float2(acc[mf][nf][2] + bia[nf].x,
                                           acc[mf][nf][3] + bia[nf].y);
                    *(float2*)&g_xlr[(size_t)(r0 + 8) * XD + c] = v;
                }
            }
        }
    }
}

__global__ __launch_bounds__(256, 2) void k_gemm_mma(int tsel, int kd) {
    extern __shared__ uint32_t smg[];
    if (kd == 128) gemm_body<128>(tsel, smg);
    else           gemm_body<64>(tsel, smg);
}

// ---------------- edge kernel: one warp per compact active dst, pipelined ----
__global__ void k_edge(const float* __restrict__ att, int t) {
    int w = (blockIdx.x * blockDim.x + threadIdx.x) >> 5;
    int lane = threadIdx.x & 31;
    int na = g_nact[t];
    if (w >= na) return;
    int norig = g_order[w];

    int j0 = lane * 8;
    const float4 at0 = *(const float4*)&att[j0];
    const float4 at1 = *(const float4*)&att[j0 + 4];
    const float* xrp = &g_xlr[(size_t)w * XD + 256 + j0];
    const float4 xr0 = *(const float4*)xrp;
    const float4 xr1 = *(const float4*)(xrp + 4);

    float acc[8];
#pragma unroll
    for (int i = 0; i < 8; i++) acc[i] = 0.f;
    float den = 0.f;

    int beg = (norig == 0) ? 0 : g_cnt[norig - 1];
    int end = g_cnt[norig];

    // software pipeline: prefetch next src row while computing current
    int cs = g_srcs[beg];
    const float* xp = &g_xlr[(size_t)cs * XD + j0];
    float4 x0 = *(const float4*)xp;
    float4 x1 = *(const float4*)(xp + 4);
    bool ca = (cs < na);

    for (int e = beg; e < end; e++) {
        float4 c0 = x0, c1 = x1;
        bool cact = ca;
        if (e + 1 < end) {
            int ns = g_srcs[e + 1];
            const float* np = &g_xlr[(size_t)ns * XD + j0];
            x0 = *(const float4*)np;
            x1 = *(const float4*)(np + 4);
            ca = (ns < na);
        }
        if (cact) {
            float p, v;
            v = c0.x + xr0.x; v = v > 0.f ? v : 0.2f * v; p  = v * at0.x;
            v = c0.y + xr0.y; v = v > 0.f ? v : 0.2f * v; p += v * at0.y;
            v = c0.z + xr0.z; v = v > 0.f ? v : 0.2f * v; p += v * at0.z;
            v = c0.w + xr0.w; v = v > 0.f ? v : 0.2f * v; p += v * at0.w;
            v = c1.x + xr1.x; v = v > 0.f ? v : 0.2f * v; p += v * at1.x;
            v = c1.y + xr1.y; v = v > 0.f ? v : 0.2f * v; p += v * at1.y;
            v = c1.z + xr1.z; v = v > 0.f ? v : 0.2f * v; p += v * at1.z;
            v = c1.w + xr1.w; v = v > 0.f ? v : 0.2f * v; p += v * at1.w;
            p += __shfl_xor_sync(0xffffffffu, p, 1);
            p += __shfl_xor_sync(0xffffffffu, p, 2);
            p += __shfl_xor_sync(0xffffffffu, p, 4);
            float ex = __expf(p);          // softmax shift-invariant
            den += ex;
            acc[0] += ex * c0.x; acc[1] += ex * c0.y;
            acc[2] += ex * c0.z; acc[3] += ex * c0.w;
            acc[4] += ex * c1.x; acc[5] += ex * c1.y;
            acc[6] += ex * c1.z; acc[7] += ex * c1.w;
        }
    }

    float rden = 1.f / fmaxf(den, 1e-16f);
    float vres[8];
#pragma unroll
    for (int i = 0; i < 8; i++) {
        float v = acc[i] * rden;
        v += __shfl_xor_sync(0xffffffffu, v, 8);
        v += __shfl_xor_sync(0xffffffffu, v, 16);
        vres[i] = v;
    }
    if (lane < 8) {
#pragma unroll
        for (int i = 0; i < 8; i++) {
            int c = lane * 8 + i;
            g_h[norig * 64 + c] = t32(tanhf(vres[i] + g_bias2[c]));
        }
    }
}

// ---------------- out = (h @ Wg + bg) * (current_state > 0) -----------------
__global__ void k_out(const float* __restrict__ Wg, const float* __restrict__ bg,
                      const int* __restrict__ cs, float* __restrict__ out) {
    __shared__ float Ws[64 * 32];
    __shared__ float hs[8][64];
    int tid = threadIdx.x;
    for (int i = tid; i < 64 * 32; i += 256) Ws[i] = Wg[i];
    for (int i = tid; i < 8 * 64; i += 256) {
        int r = blockIdx.x * 8 + (i >> 6);
        hs[i >> 6][i & 63] = (r < N_NODES) ? g_h[r * 64 + (i & 63)] : 0.f;
    }
    __syncthreads();
    int ty = tid >> 5;
    int c = tid & 31;
    int r = blockIdx.x * 8 + ty;
    if (r >= N_NODES) return;
    float s = bg[c];
#pragma unroll
    for (int k = 0; k < 64; k++) s += hs[ty][k] * Ws[k * 32 + c];
    out[r * 32 + c] = (cs[r] > 0) ? s : 0.f;
}

// ---------------- launch -----------------------------------------------------
extern "C" void kernel_launch(void* const* d_in, const int* in_sizes, int n_in,
                              void* d_out, int out_size) {
    const float* feat  = (const float*)d_in[0];
    const float* W_in  = (const float*)d_in[1];
    const float* b_in  = (const float*)d_in[2];
    const float* Wl    = (const float*)d_in[3];
    const float* bl    = (const float*)d_in[4];
    const float* Wr    = (const float*)d_in[5];
    const float* br    = (const float*)d_in[6];
    const float* att   = (const float*)d_in[7];
    const float* bconv = (const float*)d_in[8];
    const float* Wg    = (const float*)d_in[9];
    const float* bg    = (const float*)d_in[10];
    const int*   ei    = (const int*)d_in[11];
    const int*   mask  = (const int*)d_in[12];
    const int*   cstat = (const int*)d_in[13];
    float* out = (float*)d_out;

    cudaFuncSetAttribute(k_gemm_mma, cudaFuncAttributeMaxDynamicSharedMemorySize, GEMM_SMEM);

    k_l0<<<L0_GRID, 256>>>(feat, W_in, b_in, Wl, Wr, bl, br, bconv, mask);   // 0
    k_count<<<(E_EDGES + 255) / 256, 256>>>(ei);                              // 1
    k_scansc<<<1, 1024>>>(mask);                                              // 2
    k_gemm_mma<<<dim3(8, 37), 256, GEMM_SMEM>>>(0, 64);                       // 3 <- ncu
    k_fill<<<(E_EDGES + 255) / 256, 256>>>(ei);                               // 4
    k_edge<<<(N_NODES * 32) / 256, 256>>>(att, 0);                            // 5
    k_gemm_mma<<<dim3(8, 37), 256, GEMM_SMEM>>>(1, 128);                      // 6
    k_edge<<<(N_NODES * 32) / 256, 256>>>(att, 1);                            // 7
    k_gemm_mma<<<dim3(8, 37), 256, GEMM_SMEM>>>(2, 128);                      // 8
    k_edge<<<(N_NODES * 32) / 256, 256>>>(att, 2);                            // 9
    k_out<<<(N_NODES + 7) / 8, 256>>>(Wg, bg, cstat, out);                    // 10
}

// round 11
// speedup vs baseline: 1.4878x; 1.4878x over previous
#include <cuda_runtime.h>
#include <math.h>
#include <stdint.h>

#define N_NODES 50000
#define E_EDGES 200000
#define TOT_E   250000
#define HID     64
#define XD      512
#define PAD     132   // smem row pitch (words) for conflict-free frag loads

// ---------------- device scratch --------------------------------------------
__device__ int   g_beg[N_NODES];      // CSR region start per node
__device__ int   g_cnt[N_NODES + 1];  // counts, then CSR region end per node
__device__ int   g_cur[N_NODES];      // fill cursors
__device__ int   g_srcs[TOT_E];       // CSR entries as COMPACT src indices
__device__ int   g_order[N_NODES];    // compact slot -> node id (mask desc)
__device__ int   g_inv[N_NODES];      // node id -> compact slot
__device__ int   g_histp[196][4];     // per-block mask histograms
__device__ int   g_nact[4];
__device__ int   g_bcur[4];           // bucket cursors
__device__ int   g_ecur;              // CSR edge cursor
__device__ float g_h0[N_NODES * HID];
__device__ float g_h[N_NODES * HID];
__device__ float g_xlr[(size_t)(N_NODES + 128) * XD];   // compact-indexed
__device__ float g_Wp[128 * XD];      // [Wl|Wr] rows, tf32-truncated (t>0)
__device__ float g_Wsum[64 * XD];     // Wc1+Wc2 truncated (t=0, K=64)
__device__ float g_biasC[XD];
__device__ float g_bias2[HID];

__device__ __forceinline__ float t32(float v) {
    uint32_t u; asm("cvt.rna.tf32.f32 %0, %1;" : "=r"(u) : "f"(v));
    return __uint_as_float(u);
}

// ---------------- L0: fused h0 / weight-prep / Wsum / cnt-init+hist ----------
#define L0_H0   782                      // 64 rows per block
#define L0_PB   (L0_H0 + 256)
#define L0_WS   (L0_PB + 128)
#define L0_GRID (L0_WS + 196)

__global__ void k_l0(const float* __restrict__ feat, const float* __restrict__ W_in,
                     const float* __restrict__ b_in,
                     const float* __restrict__ Wl, const float* __restrict__ Wr,
                     const float* __restrict__ bl, const float* __restrict__ br,
                     const float* __restrict__ bconv, const int* __restrict__ mask) {
    __shared__ float Ws[32 * 64];
    __shared__ float fs[64][32];
    __shared__ int sh[4];
    int b = blockIdx.x, tid = threadIdx.x;
    if (b < L0_H0) {
        // h0 = feat @ W_in + b_in (64 rows per block)
        for (int i = tid; i < 32 * 64; i += 256) Ws[i] = W_in[i];
        for (int i = tid; i < 64 * 32; i += 256) {
            int r = b * 64 + (i >> 5);
            fs[i >> 5][i & 31] = (r < N_NODES) ? feat[r * 32 + (i & 31)] : 0.f;
        }
        __syncthreads();
        int rg = tid >> 6, c = tid & 63;
        float bc = b_in[c];
#pragma unroll 4
        for (int i = 0; i < 16; i++) {
            int rl = rg * 16 + i;
            int r = b * 64 + rl;
            if (r >= N_NODES) break;
            float s = bc;
#pragma unroll
            for (int k = 0; k < 32; k++) s += fs[rl][k] * Ws[k * 64 + c];
            float sv = t32(s);
            g_h0[r * 64 + c] = sv;
            g_h[r * 64 + c] = sv;
        }
    } else if (b < L0_PB) {
        int idx = (b - L0_H0) * 256 + tid;
        int k = idx >> 9, j = idx & 511;
        float v = (j < 256) ? Wl[k * 256 + j] : Wr[k * 256 + (j - 256)];
        g_Wp[idx] = t32(v);
        if (idx < XD) g_biasC[idx] = (idx < 256) ? bl[idx] : br[idx - 256];
        if (idx < HID)
            g_bias2[idx] = bconv[idx] + bconv[64 + idx] + bconv[128 + idx] + bconv[192 + idx];
    } else if (b < L0_WS) {
        int idx = (b - L0_PB) * 256 + tid;
        int k = idx >> 9, j = idx & 511;
        float v;
        if (j < 256) v = Wl[k * 256 + j] + Wl[(k + 64) * 256 + j];
        else         v = Wr[k * 256 + (j - 256)] + Wr[(k + 64) * 256 + (j - 256)];
        g_Wsum[idx] = t32(v);
    } else {
        int hb = b - L0_WS;
        if (hb == 0 && tid < 4) g_bcur[tid] = 0;
        if (hb == 0 && tid == 4) g_ecur = 0;
        if (tid < 4) sh[tid] = 0;
        __syncthreads();
        int i = hb * 256 + tid;
        if (i < N_NODES) {
            g_cnt[i] = 1;                  // self loop
            int m = mask[i]; m = m < 0 ? 0 : (m > 3 ? 3 : m);
            atomicAdd(&sh[m], 1);
        }
        __syncthreads();
        if (tid < 4) g_histp[hb][tid] = sh[tid];
    }
}

// ---------------- count incoming edges ---------------------------------------
__global__ void k_count(const int* __restrict__ ei) {
    int e = blockIdx.x * blockDim.x + threadIdx.x;
    if (e < E_EDGES) atomicAdd(&g_cnt[ei[E_EDGES + e]], 1);
}

// ---------------- parallel slot assignment (replaces serial scan) ------------
// CSR regions need only be DISJOINT, not ordered: beg = atomicAdd(cursor, cnt).
__global__ void k_assign(const int* __restrict__ mask) {
    __shared__ int hh[4];
    int tid = threadIdx.x, lane = tid & 31;
    if (tid < 4) hh[tid] = 0;
    __syncthreads();
    for (int i = tid; i < 784; i += 256)
        atomicAdd(&hh[i & 3], ((const int*)g_histp)[i]);
    __syncthreads();
    int h1 = hh[1], h2 = hh[2], h3 = hh[3];
    if (blockIdx.x == 0 && tid == 0) {
        g_nact[0] = h1 + h2 + h3; g_nact[1] = h2 + h3; g_nact[2] = h3; g_nact[3] = 0;
    }
    int i = blockIdx.x * 256 + tid;
    bool act = (i < N_NODES);
    int m = 0, cnt = 0;
    if (act) {
        m = mask[i]; m = m < 0 ? 0 : (m > 3 ? 3 : m);
        cnt = g_cnt[i];
    }
    // bucket slot: warp-aggregated atomics
    unsigned b0 = __ballot_sync(0xffffffffu, act && m == 0);
    unsigned b1 = __ballot_sync(0xffffffffu, act && m == 1);
    unsigned b2 = __ballot_sync(0xffffffffu, act && m == 2);
    unsigned b3 = __ballot_sync(0xffffffffu, act && m == 3);
    unsigned mym = (m == 0) ? b0 : (m == 1) ? b1 : (m == 2) ? b2 : b3;
    if (!act) mym = 1u;
    int rank = __popc(mym & ((1u << lane) - 1));
    int leader = __ffs(mym) - 1;
    int bbase = 0;
    if (act && lane == leader) bbase = atomicAdd(&g_bcur[m], __popc(mym));
    bbase = __shfl_sync(0xffffffffu, bbase, leader);
    int start = (m == 3) ? 0 : ((m == 2) ? h3 : ((m == 1) ? h3 + h2 : h3 + h2 + h1));
    // CSR region: warp inclusive scan of cnt + one atomic
    int sv = cnt;
#pragma unroll
    for (int d = 1; d < 32; d <<= 1) {
        int u = __shfl_up_sync(0xffffffffu, sv, d);
        if (lane >= d) sv += u;
    }
    int wtot = __shfl_sync(0xffffffffu, sv, 31);
    int ebase = 0;
    if (lane == 31) ebase = atomicAdd(&g_ecur, wtot);
    ebase = __shfl_sync(0xffffffffu, ebase, 31);
    if (act) {
        int pos = start + bbase + rank;
        int beg = ebase + sv - cnt;
        g_order[pos] = i;
        g_inv[i] = pos;
        g_beg[i] = beg;
        g_cnt[i] = beg + cnt;          // end
        g_srcs[beg] = pos;             // self loop first (compact id)
        g_cur[i] = beg + 1;
    }
}

// ---------------- fill CSR with compact src ids ------------------------------
__global__ void k_fill(const int* __restrict__ ei) {
    int e = blockIdx.x * blockDim.x + threadIdx.x;
    if (e >= E_EDGES) return;
    int d = ei[E_EDGES + e];
    int p = atomicAdd(&g_cur[d], 1);
    g_srcs[p] = g_inv[ei[e]];
}

// ---------------- HMMA tf32 GEMM v2: tile 128x128, PAD layout ----------------
// xlr[compact,512] = A @ W + biasC;  A = [h|h0] (K=128) or h (K=64 vs Wsum).
// grid (4, 37) persistent; 8 warps = 2M x 4N; regs ~160; 1 CTA/SM.
#define GEMM_SMEM (2 * 128 * PAD * 4)

template<int KD>
__device__ __forceinline__ void gemm_body(int tsel, uint32_t* smg) {
    uint32_t* As = smg;               // [128][PAD]
    uint32_t* Bs = smg + 128 * PAD;   // [KD][PAD]
    int nact = g_nact[tsel];
    int ntile = (nact + 127) >> 7;
    int colB = blockIdx.x * 128;
    int tid = threadIdx.x, lane = tid & 31, wid = tid >> 5;
    int mwarp = wid >> 2, nwarp = wid & 3;
    int group = lane >> 2, tig = lane & 3;
    const float* W = (KD == 128) ? g_Wp : g_Wsum;

    // B tile once per CTA (KD rows x 128 cols)
    for (int i = tid; i < KD * 32; i += 256) {
        int k = i >> 5, c4 = (i & 31) * 4;
        float4 v = *(const float4*)&W[k * 512 + colB + c4];
        uint32_t* d = &Bs[k * PAD + c4];
        d[0] = __float_as_uint(v.x); d[1] = __float_as_uint(v.y);
        d[2] = __float_as_uint(v.z); d[3] = __float_as_uint(v.w);
    }

    float2 bia[4];
#pragma unroll
    for (int nf = 0; nf < 4; nf++)
        bia[nf] = *(const float2*)&g_biasC[colB + nwarp * 32 + nf * 8 + 2 * tig];

    const uint32_t* aBase = &As[(mwarp * 64 + group) * PAD + tig];
    const uint32_t* bBase = &Bs[tig * PAD + nwarp * 32 + group];
    int m_st = tid >> 1, half = tid & 1;

    for (int tile = blockIdx.y; tile < ntile; tile += gridDim.y) {
        int row0 = tile << 7;
        __syncthreads();
        // ---- A stage (pure copy; h/h0 already tf32-truncated) --------------
        {
            int r = row0 + m_st;
            int gr = (r < nact) ? g_order[r] : g_order[0];
            const float4* sp;
            uint32_t* dst;
            int ncpy;
            if (KD == 128) {
                sp = (const float4*)&(half ? g_h0 : g_h)[(size_t)gr * 64];
                dst = &As[m_st * PAD + half * 64];
                ncpy = 16;
            } else {
                sp = (const float4*)&g_h[(size_t)gr * 64 + half * 32];
                dst = &As[m_st * PAD + half * 32];
                ncpy = 8;
            }
#pragma unroll
            for (int i = 0; i < ncpy; i++) {
                float4 v = sp[i];
                dst[i * 4] = __float_as_uint(v.x); dst[i * 4 + 1] = __float_as_uint(v.y);
                dst[i * 4 + 2] = __float_as_uint(v.z); dst[i * 4 + 3] = __float_as_uint(v.w);
            }
        }
        __syncthreads();

        float acc[4][4][4];
#pragma unroll
        for (int mf = 0; mf < 4; mf++)
#pragma unroll
            for (int nf = 0; nf < 4; nf++)
#pragma unroll
                for (int q = 0; q < 4; q++) acc[mf][nf][q] = 0.f;

#pragma unroll 4
        for (int k0 = 0; k0 < KD / 8; k0++) {
            uint32_t a[4][4], b[4][2];
#pragma unroll
            for (int mf = 0; mf < 4; mf++) {
                const uint32_t* ap = aBase + mf * 16 * PAD + k0 * 8;
                a[mf][0] = ap[0];
                a[mf][1] = ap[8 * PAD];
                a[mf][2] = ap[4];
                a[mf][3] = ap[8 * PAD + 4];
            }
#pragma unroll
            for (int nf = 0; nf < 4; nf++) {
                const uint32_t* bp = bBase + k0 * 8 * PAD + nf * 8;
                b[nf][0] = bp[0];
                b[nf][1] = bp[4 * PAD];
            }
#pragma unroll
            for (int mf = 0; mf < 4; mf++)
#pragma unroll
                for (int nf = 0; nf < 4; nf++) {
                    asm volatile(
                        "mma.sync.aligned.m16n8k8.row.col.f32.tf32.tf32.f32 "
                        "{%0,%1,%2,%3}, {%4,%5,%6,%7}, {%8,%9}, {%0,%1,%2,%3};"
                        : "+f"(acc[mf][nf][0]), "+f"(acc[mf][nf][1]),
                          "+f"(acc[mf][nf][2]), "+f"(acc[mf][nf][3])
                        : "r"(a[mf][0]), "r"(a[mf][1]), "r"(a[mf][2]), "r"(a[mf][3]),
                          "r"(b[nf][0]), "r"(b[nf][1]));
                }
        }

#pragma unroll
        for (int mf = 0; mf < 4; mf++) {
            int r0 = row0 + mwarp * 64 + mf * 16 + group;
#pragma unroll
            for (int nf = 0; nf < 4; nf++) {
                int c = colB + nwarp * 32 + nf * 8 + 2 * tig;
                if (r0 < nact) {
                    float2 v = make_float2(acc[mf][nf][0] + bia[nf].x,
                                           acc[mf][nf][1] + bia[nf].y);
                    *(float2*)&g_xlr[(size_t)r0 * XD + c] = v;
                }
                if (r0 + 8 < nact) {
                    float2 v = make_float2(acc[mf][nf][2] + bia[nf].x,
                                           acc[mf][nf][3] + bia[nf].y);
                    *(float2*)&g_xlr[(size_t)(r0 + 8) * XD + c] = v;
                }
            }
        }
    }
}

__global__ __launch_bounds__(256, 1) void k_gemm_mma(int tsel, int kd) {
    extern __shared__ uint32_t smg[];
    if (kd == 128) gemm_body<128>(tsel, smg);
    else           gemm_body<64>(tsel, smg);
}

// ---------------- edge kernel: one warp per compact active dst ---------------
__global__ void k_edge(const float* __restrict__ att, int t) {
    int w = (blockIdx.x * blockDim.x + threadIdx.x) >> 5;
    int lane = threadIdx.x & 31;
    int na = g_nact[t];
    if (w >= na) return;
    int norig = g_order[w];

    int j0 = lane * 8;
    const float4 at0 = *(const float4*)&att[j0];
    const float4 at1 = *(const float4*)&att[j0 + 4];
    const float* xrp = &g_xlr[(size_t)w * XD + 256 + j0];
    const float4 xr0 = *(const float4*)xrp;
    const float4 xr1 = *(const float4*)(xrp + 4);

    float acc[8];
#pragma unroll
    for (int i = 0; i < 8; i++) acc[i] = 0.f;
    float den = 0.f;

    int beg = g_beg[norig];
    int end = g_cnt[norig];
    for (int e = beg; e < end; e++) {
        int cs = g_srcs[e];
        if (cs >= na) continue;            // src inactive at step t
        const float* xp = &g_xlr[(size_t)cs * XD + j0];
        const float4 x0 = *(const float4*)xp;
        const float4 x1 = *(const float4*)(xp + 4);
        float p, v;
        v = x0.x + xr0.x; v = v > 0.f ? v : 0.2f * v; p  = v * at0.x;
        v = x0.y + xr0.y; v = v > 0.f ? v : 0.2f * v; p += v * at0.y;
        v = x0.z + xr0.z; v = v > 0.f ? v : 0.2f * v; p += v * at0.z;
        v = x0.w + xr0.w; v = v > 0.f ? v : 0.2f * v; p += v * at0.w;
        v = x1.x + xr1.x; v = v > 0.f ? v : 0.2f * v; p += v * at1.x;
        v = x1.y + xr1.y; v = v > 0.f ? v : 0.2f * v; p += v * at1.y;
        v = x1.z + xr1.z; v = v > 0.f ? v : 0.2f * v; p += v * at1.z;
        v = x1.w + xr1.w; v = v > 0.f ? v : 0.2f * v; p += v * at1.w;
        p += __shfl_xor_sync(0xffffffffu, p, 1);
        p += __shfl_xor_sync(0xffffffffu, p, 2);
        p += __shfl_xor_sync(0xffffffffu, p, 4);
        float ex = __expf(p);              // softmax shift-invariant
        den += ex;
        acc[0] += ex * x0.x; acc[1] += ex * x0.y;
        acc[2] += ex * x0.z; acc[3] += ex * x0.w;
        acc[4] += ex * x1.x; acc[5] += ex * x1.y;
        acc[6] += ex * x1.z; acc[7] += ex * x1.w;
    }

    float rden = 1.f / fmaxf(den, 1e-16f);
    float vres[8];
#pragma unroll
    for (int i = 0; i < 8; i++) {
        float v = acc[i] * rden;
        v += __shfl_xor_sync(0xffffffffu, v, 8);
        v += __shfl_xor_sync(0xffffffffu, v, 16);
        vres[i] = v;
    }
    if (lane < 8) {
#pragma unroll
        for (int i = 0; i < 8; i++) {
            int c = lane * 8 + i;
            g_h[norig * 64 + c] = t32(tanhf(vres[i] + g_bias2[c]));
        }
    }
}

// ---------------- out = (h @ Wg + bg) * (current_state > 0) -----------------
__global__ void k_out(const float* __restrict__ Wg, const float* __restrict__ bg,
                      const int* __restrict__ cs, float* __restrict__ out) {
    __shared__ float Ws[64 * 32];
    __shared__ float hs[8][64];
    int tid = threadIdx.x;
    for (int i = tid; i < 64 * 32; i += 256) Ws[i] = Wg[i];
    for (int i = tid; i < 8 * 64; i += 256) {
        int r = blockIdx.x * 8 + (i >> 6);
        hs[i >> 6][i & 63] = (r < N_NODES) ? g_h[r * 64 + (i & 63)] : 0.f;
    }
    __syncthreads();
    int ty = tid >> 5;
    int c = tid & 31;
    int r = blockIdx.x * 8 + ty;
    if (r >= N_NODES) return;
    if (cs[r] <= 0) { out[r * 32 + c] = 0.f; return; }
    float s = bg[c];
#pragma unroll
    for (int k = 0; k < 64; k++) s += hs[ty][k] * Ws[k * 32 + c];
    out[r * 32 + c] = s;
}

// ---------------- launch -----------------------------------------------------
extern "C" void kernel_launch(void* const* d_in, const int* in_sizes, int n_in,
                              void* d_out, int out_size) {
    const float* feat  = (const float*)d_in[0];
    const float* W_in  = (const float*)d_in[1];
    const float* b_in  = (const float*)d_in[2];
    const float* Wl    = (const float*)d_in[3];
    const float* bl    = (const float*)d_in[4];
    const float* Wr    = (const float*)d_in[5];
    const float* br    = (const float*)d_in[6];
    const float* att   = (const float*)d_in[7];
    const float* bconv = (const float*)d_in[8];
    const float* Wg    = (const float*)d_in[9];
    const float* bg    = (const float*)d_in[10];
    const int*   ei    = (const int*)d_in[11];
    const int*   mask  = (const int*)d_in[12];
    const int*   cstat = (const int*)d_in[13];
    float* out = (float*)d_out;

    cudaFuncSetAttribute(k_gemm_mma, cudaFuncAttributeMaxDynamicSharedMemorySize, GEMM_SMEM);

    k_l0<<<L0_GRID, 256>>>(feat, W_in, b_in, Wl, Wr, bl, br, bconv, mask);   // 0
    k_count<<<(E_EDGES + 255) / 256, 256>>>(ei);                              // 1
    k_assign<<<196, 256>>>(mask);                                             // 2
    k_gemm_mma<<<dim3(4, 37), 256, GEMM_SMEM>>>(0, 64);                       // 3 <- ncu
    k_fill<<<(E_EDGES + 255) / 256, 256>>>(ei);                               // 4
    k_edge<<<(N_NODES * 32) / 256, 256>>>(att, 0);                            // 5
    k_gemm_mma<<<dim3(4, 37), 256, GEMM_SMEM>>>(1, 128);                      // 6
    k_edge<<<(N_NODES * 32) / 256, 256>>>(att, 1);                            // 7
    k_gemm_mma<<<dim3(4, 37), 256, GEMM_SMEM>>>(2, 128);                      // 8
    k_edge<<<(N_NODES * 32) / 256, 256>>>(att, 2);                            // 9
    k_out<<<(N_NODES + 7) / 8, 256>>>(Wg, bg, cstat, out);                    // 10
}

// round 12
// speedup vs baseline: 1.5088x; 1.0141x over previous
#include <cuda_runtime.h>
#include <math.h>
#include <stdint.h>

#define N_NODES 50000
#define E_EDGES 200000
#define TOT_E   250000
#define HID     64
#define XD      512
#define PAD     132   // smem row pitch (words) for conflict-free frag loads

// ---------------- device scratch --------------------------------------------
__device__ int   g_beg[N_NODES];      // CSR region start per node
__device__ int   g_cnt[N_NODES + 1];  // counts, then CSR region end per node
__device__ int   g_cur[N_NODES];      // fill cursors
__device__ int   g_srcs[TOT_E];       // CSR entries as COMPACT src indices
__device__ int   g_order[N_NODES];    // compact slot -> node id (mask desc)
__device__ int   g_inv[N_NODES];      // node id -> compact slot
__device__ int   g_histp[196][4];     // per-block mask histograms
__device__ int   g_nact[4];
__device__ int   g_bcur[4];           // bucket cursors
__device__ int   g_ecur;              // CSR edge cursor
__device__ float g_h0[N_NODES * HID];
__device__ float g_h[N_NODES * HID];
__device__ float g_xlr[(size_t)(N_NODES + 128) * XD];   // compact-indexed
__device__ float g_Wp[128 * XD];      // [Wl|Wr] rows, tf32-truncated (t>0)
__device__ float g_Wsum[64 * XD];     // Wc1+Wc2 truncated (t=0, K=64)
__device__ float g_biasC[XD];
__device__ float g_bias2[HID];

__device__ __forceinline__ float t32(float v) {
    uint32_t u; asm("cvt.rna.tf32.f32 %0, %1;" : "=r"(u) : "f"(v));
    return __uint_as_float(u);
}

// ---------------- L0: fused h0 / weight-prep / Wsum / cnt-init+hist ----------
#define L0_H0   782                      // 64 rows per block
#define L0_PB   (L0_H0 + 256)
#define L0_WS   (L0_PB + 128)
#define L0_GRID (L0_WS + 196)

__global__ void k_l0(const float* __restrict__ feat, const float* __restrict__ W_in,
                     const float* __restrict__ b_in,
                     const float* __restrict__ Wl, const float* __restrict__ Wr,
                     const float* __restrict__ bl, const float* __restrict__ br,
                     const float* __restrict__ bconv, const int* __restrict__ mask) {
    __shared__ float Ws[32 * 64];
    __shared__ float fs[64][32];
    __shared__ int sh[4];
    int b = blockIdx.x, tid = threadIdx.x;
    if (b < L0_H0) {
        // h0 = feat @ W_in + b_in (64 rows per block)
        for (int i = tid; i < 32 * 64; i += 256) Ws[i] = W_in[i];
        for (int i = tid; i < 64 * 32; i += 256) {
            int r = b * 64 + (i >> 5);
            fs[i >> 5][i & 31] = (r < N_NODES) ? feat[r * 32 + (i & 31)] : 0.f;
        }
        __syncthreads();
        int rg = tid >> 6, c = tid & 63;
        float bc = b_in[c];
#pragma unroll 4
        for (int i = 0; i < 16; i++) {
            int rl = rg * 16 + i;
            int r = b * 64 + rl;
            if (r >= N_NODES) break;
            float s = bc;
#pragma unroll
            for (int k = 0; k < 32; k++) s += fs[rl][k] * Ws[k * 64 + c];
            float sv = t32(s);
            g_h0[r * 64 + c] = sv;
            g_h[r * 64 + c] = sv;
        }
    } else if (b < L0_PB) {
        int idx = (b - L0_H0) * 256 + tid;
        int k = idx >> 9, j = idx & 511;
        float v = (j < 256) ? Wl[k * 256 + j] : Wr[k * 256 + (j - 256)];
        g_Wp[idx] = t32(v);
        if (idx < XD) g_biasC[idx] = (idx < 256) ? bl[idx] : br[idx - 256];
        if (idx < HID)
            g_bias2[idx] = bconv[idx] + bconv[64 + idx] + bconv[128 + idx] + bconv[192 + idx];
    } else if (b < L0_WS) {
        int idx = (b - L0_PB) * 256 + tid;
        int k = idx >> 9, j = idx & 511;
        float v;
        if (j < 256) v = Wl[k * 256 + j] + Wl[(k + 64) * 256 + j];
        else         v = Wr[k * 256 + (j - 256)] + Wr[(k + 64) * 256 + (j - 256)];
        g_Wsum[idx] = t32(v);
    } else {
        int hb = b - L0_WS;
        if (hb == 0 && tid < 4) g_bcur[tid] = 0;
        if (hb == 0 && tid == 4) g_ecur = 0;
        if (tid < 4) sh[tid] = 0;
        __syncthreads();
        int i = hb * 256 + tid;
        if (i < N_NODES) {
            g_cnt[i] = 1;                  // self loop
            int m = mask[i]; m = m < 0 ? 0 : (m > 3 ? 3 : m);
            atomicAdd(&sh[m], 1);
        }
        __syncthreads();
        if (tid < 4) g_histp[hb][tid] = sh[tid];
    }
}

// ---------------- count incoming edges ---------------------------------------
__global__ void k_count(const int* __restrict__ ei) {
    int e = blockIdx.x * blockDim.x + threadIdx.x;
    if (e < E_EDGES) atomicAdd(&g_cnt[ei[E_EDGES + e]], 1);
}

// ---------------- parallel slot assignment (replaces serial scan) ------------
// CSR regions need only be DISJOINT, not ordered: beg = atomicAdd(cursor, cnt).
__global__ void k_assign(const int* __restrict__ mask) {
    __shared__ int hh[4];
    int tid = threadIdx.x, lane = tid & 31;
    if (tid < 4) hh[tid] = 0;
    __syncthreads();
    for (int i = tid; i < 784; i += 256)
        atomicAdd(&hh[i & 3], ((const int*)g_histp)[i]);
    __syncthreads();
    int h1 = hh[1], h2 = hh[2], h3 = hh[3];
    if (blockIdx.x == 0 && tid == 0) {
        g_nact[0] = h1 + h2 + h3; g_nact[1] = h2 + h3; g_nact[2] = h3; g_nact[3] = 0;
    }
    int i = blockIdx.x * 256 + tid;
    bool act = (i < N_NODES);
    int m = 0, cnt = 0;
    if (act) {
        m = mask[i]; m = m < 0 ? 0 : (m > 3 ? 3 : m);
        cnt = g_cnt[i];
    }
    // bucket slot: warp-aggregated atomics
    unsigned b0 = __ballot_sync(0xffffffffu, act && m == 0);
    unsigned b1 = __ballot_sync(0xffffffffu, act && m == 1);
    unsigned b2 = __ballot_sync(0xffffffffu, act && m == 2);
    unsigned b3 = __ballot_sync(0xffffffffu, act && m == 3);
    unsigned mym = (m == 0) ? b0 : (m == 1) ? b1 : (m == 2) ? b2 : b3;
    if (!act) mym = 1u;
    int rank = __popc(mym & ((1u << lane) - 1));
    int leader = __ffs(mym) - 1;
    int bbase = 0;
    if (act && lane == leader) bbase = atomicAdd(&g_bcur[m], __popc(mym));
    bbase = __shfl_sync(0xffffffffu, bbase, leader);
    int start = (m == 3) ? 0 : ((m == 2) ? h3 : ((m == 1) ? h3 + h2 : h3 + h2 + h1));
    // CSR region: warp inclusive scan of cnt + one atomic
    int sv = cnt;
#pragma unroll
    for (int d = 1; d < 32; d <<= 1) {
        int u = __shfl_up_sync(0xffffffffu, sv, d);
        if (lane >= d) sv += u;
    }
    int wtot = __shfl_sync(0xffffffffu, sv, 31);
    int ebase = 0;
    if (lane == 31) ebase = atomicAdd(&g_ecur, wtot);
    ebase = __shfl_sync(0xffffffffu, ebase, 31);
    if (act) {
        int pos = start + bbase + rank;
        int beg = ebase + sv - cnt;
        g_order[pos] = i;
        g_inv[i] = pos;
        g_beg[i] = beg;
        g_cnt[i] = beg + cnt;          // end
        g_srcs[beg] = pos;             // self loop first (compact id)
        g_cur[i] = beg + 1;
    }
}

// ---------------- fill CSR with compact src ids ------------------------------
__global__ void k_fill(const int* __restrict__ ei) {
    int e = blockIdx.x * blockDim.x + threadIdx.x;
    if (e >= E_EDGES) return;
    int d = ei[E_EDGES + e];
    int p = atomicAdd(&g_cur[d], 1);
    g_srcs[p] = g_inv[ei[e]];
}

// ---------------- HMMA tf32 GEMM v2p: 128x128 tile, pipelined A-stage --------
// xlr[compact,512] = A @ W + biasC;  A = [h|h0] (K=128) or h (K=64 vs Wsum).
// grid (4, 37) persistent; 8 warps = 2M x 4N; register-prefetch A pipeline.
#define GEMM_SMEM (2 * 128 * PAD * 4)

template<int KD>
__device__ __forceinline__ void gemm_body(int tsel, uint32_t* smg) {
    uint32_t* As = smg;               // [128][PAD]
    uint32_t* Bs = smg + 128 * PAD;   // [KD][PAD]
    int nact = g_nact[tsel];
    int ntile = (nact + 127) >> 7;
    int colB = blockIdx.x * 128;
    int tid = threadIdx.x, lane = tid & 31, wid = tid >> 5;
    int mwarp = wid >> 2, nwarp = wid & 3;
    int group = lane >> 2, tig = lane & 3;
    const float* W = (KD == 128) ? g_Wp : g_Wsum;
    constexpr int NCPY = (KD == 128) ? 16 : 8;    // float4 per thread
    constexpr int COFF = (KD == 128) ? 64 : 32;   // word offset per half

    // B tile once per CTA (KD rows x 128 cols)
    for (int i = tid; i < KD * 32; i += 256) {
        int k = i >> 5, c4 = (i & 31) * 4;
        float4 v = *(const float4*)&W[k * 512 + colB + c4];
        uint32_t* d = &Bs[k * PAD + c4];
        d[0] = __float_as_uint(v.x); d[1] = __float_as_uint(v.y);
        d[2] = __float_as_uint(v.z); d[3] = __float_as_uint(v.w);
    }

    float2 bia[4];
#pragma unroll
    for (int nf = 0; nf < 4; nf++)
        bia[nf] = *(const float2*)&g_biasC[colB + nwarp * 32 + nf * 8 + 2 * tig];

    const uint32_t* aBase = &As[(mwarp * 64 + group) * PAD + tig];
    const uint32_t* bBase = &Bs[tig * PAD + nwarp * 32 + group];

    // stage mapping: thread -> (row, half); conflict-free STS.128 phases
    int m_st = tid & 127, half = tid >> 7;
    float4 pf[NCPY];

    int tile = blockIdx.y;
    if (tile < ntile) {
        int r = (tile << 7) + m_st;
        int gr = (r < nact) ? g_order[r] : g_order[0];
        const float4* sp = (KD == 128)
            ? (const float4*)&(half ? g_h0 : g_h)[(size_t)gr * 64]
            : (const float4*)&g_h[(size_t)gr * 64 + half * 32];
#pragma unroll
        for (int i = 0; i < NCPY; i++) pf[i] = sp[i];
    }

    for (; tile < ntile; tile += gridDim.y) {
        __syncthreads();                 // prev tile's As reads complete
        {
            float4* dst = (float4*)&As[m_st * PAD + half * COFF];
#pragma unroll
            for (int i = 0; i < NCPY; i++) dst[i] = pf[i];
        }
        __syncthreads();                 // As ready

        // prefetch NEXT tile's A rows (latency hides behind mainloop)
        int nxt = tile + gridDim.y;
        if (nxt < ntile) {
            int r = (nxt << 7) + m_st;
            int gr = (r < nact) ? g_order[r] : g_order[0];
            const float4* sp = (KD == 128)
                ? (const float4*)&(half ? g_h0 : g_h)[(size_t)gr * 64]
                : (const float4*)&g_h[(size_t)gr * 64 + half * 32];
#pragma unroll
            for (int i = 0; i < NCPY; i++) pf[i] = sp[i];
        }

        float acc[4][4][4];
#pragma unroll
        for (int mf = 0; mf < 4; mf++)
#pragma unroll
            for (int nf = 0; nf < 4; nf++)
#pragma unroll
                for (int q = 0; q < 4; q++) acc[mf][nf][q] = 0.f;

#pragma unroll 4
        for (int k0 = 0; k0 < KD / 8; k0++) {
            uint32_t a[4][4], b[4][2];
#pragma unroll
            for (int mf = 0; mf < 4; mf++) {
                const uint32_t* ap = aBase + mf * 16 * PAD + k0 * 8;
                a[mf][0] = ap[0];
                a[mf][1] = ap[8 * PAD];
                a[mf][2] = ap[4];
                a[mf][3] = ap[8 * PAD + 4];
            }
#pragma unroll
            for (int nf = 0; nf < 4; nf++) {
                const uint32_t* bp = bBase + k0 * 8 * PAD + nf * 8;
                b[nf][0] = bp[0];
                b[nf][1] = bp[4 * PAD];
            }
#pragma unroll
            for (int mf = 0; mf < 4; mf++)
#pragma unroll
                for (int nf = 0; nf < 4; nf++) {
                    asm volatile(
                        "mma.sync.aligned.m16n8k8.row.col.f32.tf32.tf32.f32 "
                        "{%0,%1,%2,%3}, {%4,%5,%6,%7}, {%8,%9}, {%0,%1,%2,%3};"
                        : "+f"(acc[mf][nf][0]), "+f"(acc[mf][nf][1]),
                          "+f"(acc[mf][nf][2]), "+f"(acc[mf][nf][3])
                        : "r"(a[mf][0]), "r"(a[mf][1]), "r"(a[mf][2]), "r"(a[mf][3]),
                          "r"(b[nf][0]), "r"(b[nf][1]));
                }
        }

        int row0 = tile << 7;
#pragma unroll
        for (int mf = 0; mf < 4; mf++) {
            int r0 = row0 + mwarp * 64 + mf * 16 + group;
#pragma unroll
            for (int nf = 0; nf < 4; nf++) {
                int c = colB + nwarp * 32 + nf * 8 + 2 * tig;
                if (r0 < nact) {
                    float2 v = make_float2(acc[mf][nf][0] + bia[nf].x,
                                           acc[mf][nf][1] + bia[nf].y);
                    *(float2*)&g_xlr[(size_t)r0 * XD + c] = v;
                }
                if (r0 + 8 < nact) {
                    float2 v = make_float2(acc[mf][nf][2] + bia[nf].x,
                                           acc[mf][nf][3] + bia[nf].y);
                    *(float2*)&g_xlr[(size_t)(r0 + 8) * XD + c] = v;
                }
            }
        }
    }
}

__global__ __launch_bounds__(256, 1) void k_gemm_mma(int tsel, int kd) {
    extern __shared__ uint32_t smg[];
    if (kd == 128) gemm_body<128>(tsel, smg);
    else           gemm_body<64>(tsel, smg);
}

// ---------------- edge kernel: one warp per compact active dst ---------------
__global__ void k_edge(const float* __restrict__ att, int t) {
    int w = (blockIdx.x * blockDim.x + threadIdx.x) >> 5;
    int lane = threadIdx.x & 31;
    int na = g_nact[t];
    if (w >= na) return;
    int norig = g_order[w];

    int j0 = lane * 8;
    const float4 at0 = *(const float4*)&att[j0];
    const float4 at1 = *(const float4*)&att[j0 + 4];
    const float* xrp = &g_xlr[(size_t)w * XD + 256 + j0];
    const float4 xr0 = *(const float4*)xrp;
    const float4 xr1 = *(const float4*)(xrp + 4);

    float acc[8];
#pragma unroll
    for (int i = 0; i < 8; i++) acc[i] = 0.f;
    float den = 0.f;

    int beg = g_beg[norig];
    int end = g_cnt[norig];
    for (int e = beg; e < end; e++) {
        int cs = g_srcs[e];
        if (cs >= na) continue;            // src inactive at step t
        const float* xp = &g_xlr[(size_t)cs * XD + j0];
        const float4 x0 = *(const float4*)xp;
        const float4 x1 = *(const float4*)(xp + 4);
        float p, v;
        v = x0.x + xr0.x; v = v > 0.f ? v : 0.2f * v; p  = v * at0.x;
        v = x0.y + xr0.y; v = v > 0.f ? v : 0.2f * v; p += v * at0.y;
        v = x0.z + xr0.z; v = v > 0.f ? v : 0.2f * v; p += v * at0.z;
        v = x0.w + xr0.w; v = v > 0.f ? v : 0.2f * v; p += v * at0.w;
        v = x1.x + xr1.x; v = v > 0.f ? v : 0.2f * v; p += v * at1.x;
        v = x1.y + xr1.y; v = v > 0.f ? v : 0.2f * v; p += v * at1.y;
        v = x1.z + xr1.z; v = v > 0.f ? v : 0.2f * v; p += v * at1.z;
        v = x1.w + xr1.w; v = v > 0.f ? v : 0.2f * v; p += v * at1.w;
        p += __shfl_xor_sync(0xffffffffu, p, 1);
        p += __shfl_xor_sync(0xffffffffu, p, 2);
        p += __shfl_xor_sync(0xffffffffu, p, 4);
        float ex = __expf(p);              // softmax shift-invariant
        den += ex;
        acc[0] += ex * x0.x; acc[1] += ex * x0.y;
        acc[2] += ex * x0.z; acc[3] += ex * x0.w;
        acc[4] += ex * x1.x; acc[5] += ex * x1.y;
        acc[6] += ex * x1.z; acc[7] += ex * x1.w;
    }

    float rden = 1.f / fmaxf(den, 1e-16f);
    float vres[8];
#pragma unroll
    for (int i = 0; i < 8; i++) {
        float v = acc[i] * rden;
        v += __shfl_xor_sync(0xffffffffu, v, 8);
        v += __shfl_xor_sync(0xffffffffu, v, 16);
        vres[i] = v;
    }
    if (lane < 8) {
#pragma unroll
        for (int i = 0; i < 8; i++) {
            int c = lane * 8 + i;
            g_h[norig * 64 + c] = t32(tanhf(vres[i] + g_bias2[c]));
        }
    }
}

// ---------------- out = (h @ Wg + bg) * (current_state > 0) -----------------
__global__ void k_out(const float* __restrict__ Wg, const float* __restrict__ bg,
                      const int* __restrict__ cs, float* __restrict__ out) {
    __shared__ float Ws[64 * 32];
    __shared__ float hs[8][64];
    int tid = threadIdx.x;
    for (int i = tid; i < 64 * 32; i += 256) Ws[i] = Wg[i];
    for (int i = tid; i < 8 * 64; i += 256) {
        int r = blockIdx.x * 8 + (i >> 6);
        hs[i >> 6][i & 63] = (r < N_NODES) ? g_h[r * 64 + (i & 63)] : 0.f;
    }
    __syncthreads();
    int ty = tid >> 5;
    int c = tid & 31;
    int r = blockIdx.x * 8 + ty;
    if (r >= N_NODES) return;
    if (cs[r] <= 0) { out[r * 32 + c] = 0.f; return; }
    float s = bg[c];
#pragma unroll
    for (int k = 0; k < 64; k++) s += hs[ty][k] * Ws[k * 32 + c];
    out[r * 32 + c] = s;
}

// ---------------- launch -----------------------------------------------------
extern "C" void kernel_launch(void* const* d_in, const int* in_sizes, int n_in,
                              void* d_out, int out_size) {
    const float* feat  = (const float*)d_in[0];
    const float* W_in  = (const float*)d_in[1];
    const float* b_in  = (const float*)d_in[2];
    const float* Wl    = (const float*)d_in[3];
    const float* bl    = (const float*)d_in[4];
    const float* Wr    = (const float*)d_in[5];
    const float* br    = (const float*)d_in[6];
    const float* att   = (const float*)d_in[7];
    const float* bconv = (const float*)d_in[8];
    const float* Wg    = (const float*)d_in[9];
    const float* bg    = (const float*)d_in[10];
    const int*   ei    = (const int*)d_in[11];
    const int*   mask  = (const int*)d_in[12];
    const int*   cstat = (const int*)d_in[13];
    float* out = (float*)d_out;

    cudaFuncSetAttribute(k_gemm_mma, cudaFuncAttributeMaxDynamicSharedMemorySize, GEMM_SMEM);

    k_l0<<<L0_GRID, 256>>>(feat, W_in, b_in, Wl, Wr, bl, br, bconv, mask);   // 0
    k_count<<<(E_EDGES + 255) / 256, 256>>>(ei);                              // 1
    k_assign<<<196, 256>>>(mask);                                             // 2
    k_gemm_mma<<<dim3(4, 37), 256, GEMM_SMEM>>>(0, 64);                       // 3 <- ncu
    k_fill<<<(E_EDGES + 255) / 256, 256>>>(ei);                               // 4
    k_edge<<<(N_NODES * 32) / 256, 256>>>(att, 0);                            // 5
    k_gemm_mma<<<dim3(4, 37), 256, GEMM_SMEM>>>(1, 128);                      // 6
    k_edge<<<(N_NODES * 32) / 256, 256>>>(att, 1);                            // 7
    k_gemm_mma<<<dim3(4, 37), 256, GEMM_SMEM>>>(2, 128);                      // 8
    k_edge<<<(N_NODES * 32) / 256, 256>>>(att, 2);                            // 9
    k_out<<<(N_NODES + 7) / 8, 256>>>(Wg, bg, cstat, out);                    // 10
}

// round 14
// speedup vs baseline: 1.5238x; 1.0099x over previous
#include <cuda_runtime.h>
#include <math.h>
#include <stdint.h>

#define N_NODES 50000
#define E_EDGES 200000
#define TOT_E   250000
#define HID     64
#define XD      512
#define PAD     132   // smem row pitch (words) for conflict-free frag loads

// ---------------- device scratch --------------------------------------------
__device__ int   g_beg[N_NODES];      // CSR region start per node
__device__ int   g_cnt[N_NODES + 1];  // counts, then CSR region end per node
__device__ int   g_cur[N_NODES];      // fill cursors
__device__ int   g_srcs[TOT_E];       // CSR entries as COMPACT src indices
__device__ int   g_order[N_NODES];    // compact slot -> node id (mask desc)
__device__ int   g_inv[N_NODES];      // node id -> compact slot
__device__ int   g_histp[196][4];     // per-block mask histograms
__device__ int   g_nact[4];
__device__ int   g_bcur[4];           // bucket cursors
__device__ int   g_ecur;              // CSR edge cursor
__device__ float g_h0[N_NODES * HID];
__device__ float g_h[N_NODES * HID];
__device__ float g_xlr[(size_t)(N_NODES + 128) * XD];   // compact-indexed
__device__ float g_Wp[128 * XD];      // [Wl|Wr] rows, tf32-truncated (t>0)
__device__ float g_Wsum[64 * XD];     // Wc1+Wc2 truncated (t=0, K=64)
__device__ float g_biasC[XD];
__device__ float g_bias2[HID];

__device__ __forceinline__ float t32(float v) {
    uint32_t u; asm("cvt.rna.tf32.f32 %0, %1;" : "=r"(u) : "f"(v));
    return __uint_as_float(u);
}

// ---------------- L0: fused h0 / weight-prep / Wsum / cnt-init+hist ----------
#define L0_H0   782                      // 64 rows per block
#define L0_PB   (L0_H0 + 256)
#define L0_WS   (L0_PB + 128)
#define L0_GRID (L0_WS + 196)

__global__ void k_l0(const float* __restrict__ feat, const float* __restrict__ W_in,
                     const float* __restrict__ b_in,
                     const float* __restrict__ Wl, const float* __restrict__ Wr,
                     const float* __restrict__ bl, const float* __restrict__ br,
                     const float* __restrict__ bconv, const int* __restrict__ mask) {
    __shared__ float Ws[32 * 64];
    __shared__ float fs[64][32];
    __shared__ int sh[4];
    int b = blockIdx.x, tid = threadIdx.x;
    if (b < L0_H0) {
        // h0 = feat @ W_in + b_in (64 rows per block)
        for (int i = tid; i < 32 * 64; i += 256) Ws[i] = W_in[i];
        for (int i = tid; i < 64 * 32; i += 256) {
            int r = b * 64 + (i >> 5);
            fs[i >> 5][i & 31] = (r < N_NODES) ? feat[r * 32 + (i & 31)] : 0.f;
        }
        __syncthreads();
        int rg = tid >> 6, c = tid & 63;
        float bc = b_in[c];
#pragma unroll 4
        for (int i = 0; i < 16; i++) {
            int rl = rg * 16 + i;
            int r = b * 64 + rl;
            if (r >= N_NODES) break;
            float s = bc;
#pragma unroll
            for (int k = 0; k < 32; k++) s += fs[rl][k] * Ws[k * 64 + c];
            float sv = t32(s);
            g_h0[r * 64 + c] = sv;
            g_h[r * 64 + c] = sv;
        }
    } else if (b < L0_PB) {
        int idx = (b - L0_H0) * 256 + tid;
        int k = idx >> 9, j = idx & 511;
        float v = (j < 256) ? Wl[k * 256 + j] : Wr[k * 256 + (j - 256)];
        g_Wp[idx] = t32(v);
        if (idx < XD) g_biasC[idx] = (idx < 256) ? bl[idx] : br[idx - 256];
        if (idx < HID)
            g_bias2[idx] = bconv[idx] + bconv[64 + idx] + bconv[128 + idx] + bconv[192 + idx];
    } else if (b < L0_WS) {
        int idx = (b - L0_PB) * 256 + tid;
        int k = idx >> 9, j = idx & 511;
        float v;
        if (j < 256) v = Wl[k * 256 + j] + Wl[(k + 64) * 256 + j];
        else         v = Wr[k * 256 + (j - 256)] + Wr[(k + 64) * 256 + (j - 256)];
        g_Wsum[idx] = t32(v);
    } else {
        int hb = b - L0_WS;
        if (hb == 0 && tid < 4) g_bcur[tid] = 0;
        if (hb == 0 && tid == 4) g_ecur = 0;
        if (tid < 4) sh[tid] = 0;
        __syncthreads();
        int i = hb * 256 + tid;
        if (i < N_NODES) {
            g_cnt[i] = 1;                  // self loop
            int m = mask[i]; m = m < 0 ? 0 : (m > 3 ? 3 : m);
            atomicAdd(&sh[m], 1);
        }
        __syncthreads();
        if (tid < 4) g_histp[hb][tid] = sh[tid];
    }
}

// ---------------- count incoming edges ---------------------------------------
__global__ void k_count(const int* __restrict__ ei) {
    int e = blockIdx.x * blockDim.x + threadIdx.x;
    if (e < E_EDGES) atomicAdd(&g_cnt[ei[E_EDGES + e]], 1);
}

// ---------------- parallel slot assignment -----------------------------------
// CSR regions need only be DISJOINT, not ordered: beg = atomicAdd(cursor, cnt).
__global__ void k_assign(const int* __restrict__ mask) {
    __shared__ int hh[4];
    int tid = threadIdx.x, lane = tid & 31;
    if (tid < 4) hh[tid] = 0;
    __syncthreads();
    for (int i = tid; i < 784; i += 256)
        atomicAdd(&hh[i & 3], ((const int*)g_histp)[i]);
    __syncthreads();
    int h1 = hh[1], h2 = hh[2], h3 = hh[3];
    if (blockIdx.x == 0 && tid == 0) {
        g_nact[0] = h1 + h2 + h3; g_nact[1] = h2 + h3; g_nact[2] = h3; g_nact[3] = 0;
    }
    int i = blockIdx.x * 256 + tid;
    bool act = (i < N_NODES);
    int m = 0, cnt = 0;
    if (act) {
        m = mask[i]; m = m < 0 ? 0 : (m > 3 ? 3 : m);
        cnt = g_cnt[i];
    }
    // bucket slot: warp-aggregated atomics
    unsigned b0 = __ballot_sync(0xffffffffu, act && m == 0);
    unsigned b1 = __ballot_sync(0xffffffffu, act && m == 1);
    unsigned b2 = __ballot_sync(0xffffffffu, act && m == 2);
    unsigned b3 = __ballot_sync(0xffffffffu, act && m == 3);
    unsigned mym = (m == 0) ? b0 : (m == 1) ? b1 : (m == 2) ? b2 : b3;
    if (!act) mym = 1u;
    int rank = __popc(mym & ((1u << lane) - 1));
    int leader = __ffs(mym) - 1;
    int bbase = 0;
    if (act && lane == leader) bbase = atomicAdd(&g_bcur[m], __popc(mym));
    bbase = __shfl_sync(0xffffffffu, bbase, leader);
    int start = (m == 3) ? 0 : ((m == 2) ? h3 : ((m == 1) ? h3 + h2 : h3 + h2 + h1));
    // CSR region: warp inclusive scan of cnt + one atomic
    int sv = cnt;
#pragma unroll
    for (int d = 1; d < 32; d <<= 1) {
        int u = __shfl_up_sync(0xffffffffu, sv, d);
        if (lane >= d) sv += u;
    }
    int wtot = __shfl_sync(0xffffffffu, sv, 31);
    int ebase = 0;
    if (lane == 31) ebase = atomicAdd(&g_ecur, wtot);
    ebase = __shfl_sync(0xffffffffu, ebase, 31);
    if (act) {
        int pos = start + bbase + rank;
        int beg = ebase + sv - cnt;
        g_order[pos] = i;
        g_inv[i] = pos;
        g_beg[i] = beg;
        g_cnt[i] = beg + cnt;          // end
        g_srcs[beg] = pos;             // self loop first (compact id)
        g_cur[i] = beg + 1;
    }
}

// ---------------- fill CSR with compact src ids ------------------------------
__global__ void k_fill(const int* __restrict__ ei) {
    int e = blockIdx.x * blockDim.x + threadIdx.x;
    if (e >= E_EDGES) return;
    int d = ei[E_EDGES + e];
    int p = atomicAdd(&g_cur[d], 1);
    g_srcs[p] = g_inv[ei[e]];
}

// ---------------- HMMA tf32 GEMM v4: 128x128 tile, 512 threads / 16 warps ----
// xlr[compact,512] = A @ W + biasC;  A = [h|h0] (K=128) or h (K=64 vs Wsum).
// grid (4, 37) persistent; 16 warps = 4M x 4N, warp tile 32x32 (mf=2).
#define GEMM_SMEM (2 * 128 * PAD * 4)
#define GT 512

template<int KD>
__device__ __forceinline__ void gemm_body(int tsel, uint32_t* smg) {
    uint32_t* As = smg;               // [128][PAD]
    uint32_t* Bs = smg + 128 * PAD;   // [KD][PAD]
    int nact = g_nact[tsel];
    int ntile = (nact + 127) >> 7;
    int colB = blockIdx.x * 128;
    int tid = threadIdx.x, lane = tid & 31, wid = tid >> 5;
    int mwarp = wid >> 2, nwarp = wid & 3;      // 4M x 4N
    int group = lane >> 2, tig = lane & 3;
    const float* W = (KD == 128) ? g_Wp : g_Wsum;
    constexpr int NCPY = (KD == 128) ? 8 : 4;   // float4 per thread (stage)
    constexpr int SEGW = (KD == 128) ? 32 : 16; // floats per stage segment

    // B tile once per CTA (KD rows x 128 cols)
    for (int i = tid; i < KD * 32; i += GT) {
        int k = i >> 5, c4 = (i & 31) * 4;
        float4 v = *(const float4*)&W[k * 512 + colB + c4];
        uint32_t* d = &Bs[k * PAD + c4];
        d[0] = __float_as_uint(v.x); d[1] = __float_as_uint(v.y);
        d[2] = __float_as_uint(v.z); d[3] = __float_as_uint(v.w);
    }

    float2 bia[4];
#pragma unroll
    for (int nf = 0; nf < 4; nf++)
        bia[nf] = *(const float2*)&g_biasC[colB + nwarp * 32 + nf * 8 + 2 * tig];

    const uint32_t* aBase = &As[(mwarp * 32 + group) * PAD + tig];
    const uint32_t* bBase = &Bs[tig * PAD + nwarp * 32 + group];

    // stage mapping: row = tid&127, segment = tid>>7 (4 segments of SEGW floats)
    int m_st = tid & 127, seg = tid >> 7;
    float4 pf[NCPY];

    auto srcp = [&](int gr) -> const float4* {
        if (KD == 128) {
            const float* s = (seg >= 2) ? g_h0 : g_h;
            return (const float4*)&s[(size_t)gr * 64 + (seg & 1) * 32];
        } else {
            return (const float4*)&g_h[(size_t)gr * 64 + seg * 16];
        }
    };

    int tile = blockIdx.y;
    if (tile < ntile) {
        int r = (tile << 7) + m_st;
        const float4* sp = srcp((r < nact) ? g_order[r] : g_order[0]);
#pragma unroll
        for (int i = 0; i < NCPY; i++) pf[i] = sp[i];
    }

    for (; tile < ntile; tile += gridDim.y) {
        __syncthreads();                 // prev tile's As reads complete
        {
            float4* dst = (float4*)&As[m_st * PAD + seg * SEGW];
#pragma unroll
            for (int i = 0; i < NCPY; i++) dst[i] = pf[i];
        }
        __syncthreads();                 // As ready

        // prefetch NEXT tile's A rows (latency hides behind mainloop)
        int nxt = tile + gridDim.y;
        if (nxt < ntile) {
            int r = (nxt << 7) + m_st;
            const float4* sp = srcp((r < nact) ? g_order[r] : g_order[0]);
#pragma unroll
            for (int i = 0; i < NCPY; i++) pf[i] = sp[i];
        }

        float acc[2][4][4];
#pragma unroll
        for (int mf = 0; mf < 2; mf++)
#pragma unroll
            for (int nf = 0; nf < 4; nf++)
#pragma unroll
                for (int q = 0; q < 4; q++) acc[mf][nf][q] = 0.f;

#pragma unroll 4
        for (int k0 = 0; k0 < KD / 8; k0++) {
            uint32_t a[2][4], b[4][2];
#pragma unroll
            for (int mf = 0; mf < 2; mf++) {
                const uint32_t* ap = aBase + mf * 16 * PAD + k0 * 8;
                a[mf][0] = ap[0];
                a[mf][1] = ap[8 * PAD];
                a[mf][2] = ap[4];
                a[mf][3] = ap[8 * PAD + 4];
            }
#pragma unroll
            for (int nf = 0; nf < 4; nf++) {
                const uint32_t* bp = bBase + k0 * 8 * PAD + nf * 8;
                b[nf][0] = bp[0];
                b[nf][1] = bp[4 * PAD];
            }
#pragma unroll
            for (int mf = 0; mf < 2; mf++)
#pragma unroll
                for (int nf = 0; nf < 4; nf++) {
                    asm volatile(
                        "mma.sync.aligned.m16n8k8.row.col.f32.tf32.tf32.f32 "
                        "{%0,%1,%2,%3}, {%4,%5,%6,%7}, {%8,%9}, {%0,%1,%2,%3};"
                        : "+f"(acc[mf][nf][0]), "+f"(acc[mf][nf][1]),
                          "+f"(acc[mf][nf][2]), "+f"(acc[mf][nf][3])
                        : "r"(a[mf][0]), "r"(a[mf][1]), "r"(a[mf][2]), "r"(a[mf][3]),
                          "r"(b[nf][0]), "r"(b[nf][1]));
                }
        }

        int row0 = tile << 7;
#pragma unroll
        for (int mf = 0; mf < 2; mf++) {
            int r0 = row0 + mwarp * 32 + mf * 16 + group;
#pragma unroll
            for (int nf = 0; nf < 4; nf++) {
                int c = colB + nwarp * 32 + nf * 8 + 2 * tig;
                if (r0 < nact) {
                    float2 v = make_float2(acc[mf][nf][0] + bia[nf].x,
                                           acc[mf][nf][1] + bia[nf].y);
                    *(float2*)&g_xlr[(size_t)r0 * XD + c] = v;
                }
                if (r0 + 8 < nact) {
                    float2 v = make_float2(acc[mf][nf][2] + bia[nf].x,
                                           acc[mf][nf][3] + bia[nf].y);
                    *(float2*)&g_xlr[(size_t)(r0 + 8) * XD + c] = v;
                }
            }
        }
    }
}

__global__ __launch_bounds__(GT, 1) void k_gemm_mma(int tsel, int kd) {
    extern __shared__ uint32_t smg[];
    if (kd == 128) gemm_body<128>(tsel, smg);
    else           gemm_body<64>(tsel, smg);
}

// ---------------- edge kernel: one warp per compact active dst ---------------
__global__ void k_edge(const float* __restrict__ att, int t) {
    int w = (blockIdx.x * blockDim.x + threadIdx.x) >> 5;
    int lane = threadIdx.x & 31;
    int na = g_nact[t];
    if (w >= na) return;
    int norig = g_order[w];

    int j0 = lane * 8;
    const float4 at0 = *(const float4*)&att[j0];
    const float4 at1 = *(const float4*)&att[j0 + 4];
    const float* xrp = &g_xlr[(size_t)w * XD + 256 + j0];
    const float4 xr0 = *(const float4*)xrp;
    const float4 xr1 = *(const float4*)(xrp + 4);

    float acc[8];
#pragma unroll
    for (int i = 0; i < 8; i++) acc[i] = 0.f;
    float den = 0.f;

    int beg = g_beg[norig];
    int end = g_cnt[norig];
    for (int e = beg; e < end; e++) {
        int cs = g_srcs[e];
        if (cs >= na) continue;            // src inactive at step t
        const float* xp = &g_xlr[(size_t)cs * XD + j0];
        const float4 x0 = *(const float4*)xp;
        const float4 x1 = *(const float4*)(xp + 4);
        float p, v;
        v = x0.x + xr0.x; v = v > 0.f ? v : 0.2f * v; p  = v * at0.x;
        v = x0.y + xr0.y; v = v > 0.f ? v : 0.2f * v; p += v * at0.y;
        v = x0.z + xr0.z; v = v > 0.f ? v : 0.2f * v; p += v * at0.z;
        v = x0.w + xr0.w; v = v > 0.f ? v : 0.2f * v; p += v * at0.w;
        v = x1.x + xr1.x; v = v > 0.f ? v : 0.2f * v; p += v * at1.x;
        v = x1.y + xr1.y; v = v > 0.f ? v : 0.2f * v; p += v * at1.y;
        v = x1.z + xr1.z; v = v > 0.f ? v : 0.2f * v; p += v * at1.z;
        v = x1.w + xr1.w; v = v > 0.f ? v : 0.2f * v; p += v * at1.w;
        p += __shfl_xor_sync(0xffffffffu, p, 1);
        p += __shfl_xor_sync(0xffffffffu, p, 2);
        p += __shfl_xor_sync(0xffffffffu, p, 4);
        float ex = __expf(p);              // softmax shift-invariant
        den += ex;
        acc[0] += ex * x0.x; acc[1] += ex * x0.y;
        acc[2] += ex * x0.z; acc[3] += ex * x0.w;
        acc[4] += ex * x1.x; acc[5] += ex * x1.y;
        acc[6] += ex * x1.z; acc[7] += ex * x1.w;
    }

    float rden = 1.f / fmaxf(den, 1e-16f);
    float vres[8];
#pragma unroll
    for (int i = 0; i < 8; i++) {
        float v = acc[i] * rden;
        v += __shfl_xor_sync(0xffffffffu, v, 8);
        v += __shfl_xor_sync(0xffffffffu, v, 16);
        vres[i] = v;
    }
    if (lane < 8) {
#pragma unroll
        for (int i = 0; i < 8; i++) {
            int c = lane * 8 + i;
            g_h[norig * 64 + c] = t32(tanhf(vres[i] + g_bias2[c]));
        }
    }
}

// ---------------- out = (h @ Wg + bg) * (current_state > 0) -----------------
__global__ void k_out(const float* __restrict__ Wg, const float* __restrict__ bg,
                      const int* __restrict__ cs, float* __restrict__ out) {
    __shared__ float Ws[64 * 32];
    __shared__ float hs[8][64];
    int tid = threadIdx.x;
    for (int i = tid; i < 64 * 32; i += 256) Ws[i] = Wg[i];
    for (int i = tid; i < 8 * 64; i += 256) {
        int r = blockIdx.x * 8 + (i >> 6);
        hs[i >> 6][i & 63] = (r < N_NODES) ? g_h[r * 64 + (i & 63)] : 0.f;
    }
    __syncthreads();
    int ty = tid >> 5;
    int c = tid & 31;
    int r = blockIdx.x * 8 + ty;
    if (r >= N_NODES) return;
    if (cs[r] <= 0) { out[r * 32 + c] = 0.f; return; }
    float s = bg[c];
#pragma unroll
    for (int k = 0; k < 64; k++) s += hs[ty][k] * Ws[k * 32 + c];
    out[r * 32 + c] = s;
}

// ---------------- launch -----------------------------------------------------
extern "C" void kernel_launch(void* const* d_in, const int* in_sizes, int n_in,
                              void* d_out, int out_size) {
    const float* feat  = (const float*)d_in[0];
    const float* W_in  = (const float*)d_in[1];
    const float* b_in  = (const float*)d_in[2];
    const float* Wl    = (const float*)d_in[3];
    const float* bl    = (const float*)d_in[4];
    const float* Wr    = (const float*)d_in[5];
    const float* br    = (const float*)d_in[6];
    const float* att   = (const float*)d_in[7];
    const float* bconv = (const float*)d_in[8];
    const float* Wg    = (const float*)d_in[9];
    const float* bg    = (const float*)d_in[10];
    const int*   ei    = (const int*)d_in[11];
    const int*   mask  = (const int*)d_in[12];
    const int*   cstat = (const int*)d_in[13];
    float* out = (float*)d_out;

    cudaFuncSetAttribute(k_gemm_mma, cudaFuncAttributeMaxDynamicSharedMemorySize, GEMM_SMEM);

    k_l0<<<L0_GRID, 256>>>(feat, W_in, b_in, Wl, Wr, bl, br, bconv, mask);   // 0
    k_count<<<(E_EDGES + 255) / 256, 256>>>(ei);                              // 1
    k_assign<<<196, 256>>>(mask);                                             // 2
    k_gemm_mma<<<dim3(4, 37), GT, GEMM_SMEM>>>(0, 64);                        // 3 <- ncu
    k_fill<<<(E_EDGES + 255) / 256, 256>>>(ei);                               // 4
    k_edge<<<(N_NODES * 32) / 256, 256>>>(att, 0);                            // 5
    k_gemm_mma<<<dim3(4, 37), GT, GEMM_SMEM>>>(1, 128);                       // 6
    k_edge<<<(N_NODES * 32) / 256, 256>>>(att, 1);                            // 7
    k_gemm_mma<<<dim3(4, 37), GT, GEMM_SMEM>>>(2, 128);                       // 8
    k_edge<<<(N_NODES * 32) / 256, 256>>>(att, 2);                            // 9
    k_out<<<(N_NODES + 7) / 8, 256>>>(Wg, bg, cstat, out);                    // 10
}

// round 16
// speedup vs baseline: 1.6109x; 1.0572x over previous
#include <cuda_runtime.h>
#include <math.h>
#include <stdint.h>

#define N_NODES 50000
#define E_EDGES 200000
#define TOT_E   250000
#define HID     64
#define XD      512
#define PAD     132   // smem row pitch (words): conflict-free LDSM bursts

// ---------------- device scratch --------------------------------------------
__device__ int   g_beg[N_NODES];      // CSR region start per node
__device__ int   g_cnt[N_NODES + 1];  // counts, then CSR region end per node
__device__ int   g_cur[N_NODES];      // fill cursors
__device__ int   g_srcs[TOT_E];       // CSR entries as COMPACT src indices
__device__ int   g_order[N_NODES];    // compact slot -> node id (mask desc)
__device__ int   g_inv[N_NODES];      // node id -> compact slot
__device__ int   g_histp[196][4];     // per-block mask histograms
__device__ int   g_nact[4];
__device__ int   g_bcur[4];           // bucket cursors
__device__ int   g_ecur;              // CSR edge cursor
__device__ float g_h0[N_NODES * HID];
__device__ float g_h[N_NODES * HID];
__device__ float g_xlr[(size_t)(N_NODES + 128) * XD];   // compact-indexed
__device__ float g_WpT[XD * 128];     // W' TRANSPOSED: [n][k], tf32 (t>0)
__device__ float g_WsumT[XD * 64];    // Wsum TRANSPOSED: [n][k], tf32 (t=0)
__device__ float g_biasC[XD];
__device__ float g_bias2[HID];

__device__ __forceinline__ float t32(float v) {
    uint32_t u; asm("cvt.rna.tf32.f32 %0, %1;" : "=r"(u) : "f"(v));
    return __uint_as_float(u);
}

#define LDSM4(r, addr) \
    asm volatile("ldmatrix.sync.aligned.m8n8.x4.shared.b16 {%0,%1,%2,%3}, [%4];" \
                 : "=r"((r)[0]), "=r"((r)[1]), "=r"((r)[2]), "=r"((r)[3]) \
                 : "r"(addr))

// ---------------- L0: fused h0 / weight-prep / Wsum / cnt-init+hist ----------
#define L0_H0   782                      // 64 rows per block
#define L0_PB   (L0_H0 + 256)
#define L0_WS   (L0_PB + 128)
#define L0_GRID (L0_WS + 196)

__global__ void k_l0(const float* __restrict__ feat, const float* __restrict__ W_in,
                     const float* __restrict__ b_in,
                     const float* __restrict__ Wl, const float* __restrict__ Wr,
                     const float* __restrict__ bl, const float* __restrict__ br,
                     const float* __restrict__ bconv, const int* __restrict__ mask) {
    __shared__ float Ws[32 * 64];
    __shared__ float fs[64][32];
    __shared__ int sh[4];
    int b = blockIdx.x, tid = threadIdx.x;
    if (b < L0_H0) {
        // h0 = feat @ W_in + b_in (64 rows per block)
        for (int i = tid; i < 32 * 64; i += 256) Ws[i] = W_in[i];
        for (int i = tid; i < 64 * 32; i += 256) {
            int r = b * 64 + (i >> 5);
            fs[i >> 5][i & 31] = (r < N_NODES) ? feat[r * 32 + (i & 31)] : 0.f;
        }
        __syncthreads();
        int rg = tid >> 6, c = tid & 63;
        float bc = b_in[c];
#pragma unroll 4
        for (int i = 0; i < 16; i++) {
            int rl = rg * 16 + i;
            int r = b * 64 + rl;
            if (r >= N_NODES) break;
            float s = bc;
#pragma unroll
            for (int k = 0; k < 32; k++) s += fs[rl][k] * Ws[k * 64 + c];
            float sv = t32(s);
            g_h0[r * 64 + c] = sv;
            g_h[r * 64 + c] = sv;
        }
    } else if (b < L0_PB) {
        int idx = (b - L0_H0) * 256 + tid;
        int k = idx >> 9, j = idx & 511;
        float v = (j < 256) ? Wl[k * 256 + j] : Wr[k * 256 + (j - 256)];
        g_WpT[j * 128 + k] = t32(v);          // transposed: [n][k]
        if (idx < XD) g_biasC[idx] = (idx < 256) ? bl[idx] : br[idx - 256];
        if (idx < HID)
            g_bias2[idx] = bconv[idx] + bconv[64 + idx] + bconv[128 + idx] + bconv[192 + idx];
    } else if (b < L0_WS) {
        int idx = (b - L0_PB) * 256 + tid;
        int k = idx >> 9, j = idx & 511;
        float v;
        if (j < 256) v = Wl[k * 256 + j] + Wl[(k + 64) * 256 + j];
        else         v = Wr[k * 256 + (j - 256)] + Wr[(k + 64) * 256 + (j - 256)];
        g_WsumT[j * 64 + k] = t32(v);         // transposed: [n][k]
    } else {
        int hb = b - L0_WS;
        if (hb == 0 && tid < 4) g_bcur[tid] = 0;
        if (hb == 0 && tid == 4) g_ecur = 0;
        if (tid < 4) sh[tid] = 0;
        __syncthreads();
        int i = hb * 256 + tid;
        if (i < N_NODES) {
            g_cnt[i] = 1;                  // self loop
            int m = mask[i]; m = m < 0 ? 0 : (m > 3 ? 3 : m);
            atomicAdd(&sh[m], 1);
        }
        __syncthreads();
        if (tid < 4) g_histp[hb][tid] = sh[tid];
    }
}

// ---------------- count incoming edges ---------------------------------------
__global__ void k_count(const int* __restrict__ ei) {
    int e = blockIdx.x * blockDim.x + threadIdx.x;
    if (e < E_EDGES) atomicAdd(&g_cnt[ei[E_EDGES + e]], 1);
}

// ---------------- parallel slot assignment -----------------------------------
__global__ void k_assign(const int* __restrict__ mask) {
    __shared__ int hh[4];
    int tid = threadIdx.x, lane = tid & 31;
    if (tid < 4) hh[tid] = 0;
    __syncthreads();
    for (int i = tid; i < 784; i += 256)
        atomicAdd(&hh[i & 3], ((const int*)g_histp)[i]);
    __syncthreads();
    int h1 = hh[1], h2 = hh[2], h3 = hh[3];
    if (blockIdx.x == 0 && tid == 0) {
        g_nact[0] = h1 + h2 + h3; g_nact[1] = h2 + h3; g_nact[2] = h3; g_nact[3] = 0;
    }
    int i = blockIdx.x * 256 + tid;
    bool act = (i < N_NODES);
    int m = 0, cnt = 0;
    if (act) {
        m = mask[i]; m = m < 0 ? 0 : (m > 3 ? 3 : m);
        cnt = g_cnt[i];
    }
    unsigned b0 = __ballot_sync(0xffffffffu, act && m == 0);
    unsigned b1 = __ballot_sync(0xffffffffu, act && m == 1);
    unsigned b2 = __ballot_sync(0xffffffffu, act && m == 2);
    unsigned b3 = __ballot_sync(0xffffffffu, act && m == 3);
    unsigned mym = (m == 0) ? b0 : (m == 1) ? b1 : (m == 2) ? b2 : b3;
    if (!act) mym = 1u;
    int rank = __popc(mym & ((1u << lane) - 1));
    int leader = __ffs(mym) - 1;
    int bbase = 0;
    if (act && lane == leader) bbase = atomicAdd(&g_bcur[m], __popc(mym));
    bbase = __shfl_sync(0xffffffffu, bbase, leader);
    int start = (m == 3) ? 0 : ((m == 2) ? h3 : ((m == 1) ? h3 + h2 : h3 + h2 + h1));
    int sv = cnt;
#pragma unroll
    for (int d = 1; d < 32; d <<= 1) {
        int u = __shfl_up_sync(0xffffffffu, sv, d);
        if (lane >= d) sv += u;
    }
    int wtot = __shfl_sync(0xffffffffu, sv, 31);
    int ebase = 0;
    if (lane == 31) ebase = atomicAdd(&g_ecur, wtot);
    ebase = __shfl_sync(0xffffffffu, ebase, 31);
    if (act) {
        int pos = start + bbase + rank;
        int beg = ebase + sv - cnt;
        g_order[pos] = i;
        g_inv[i] = pos;
        g_beg[i] = beg;
        g_cnt[i] = beg + cnt;          // end
        g_srcs[beg] = pos;             // self loop first (compact id)
        g_cur[i] = beg + 1;
    }
}

// ---------------- fill CSR with compact src ids ------------------------------
__global__ void k_fill(const int* __restrict__ ei) {
    int e = blockIdx.x * blockDim.x + threadIdx.x;
    if (e >= E_EDGES) return;
    int d = ei[E_EDGES + e];
    int p = atomicAdd(&g_cur[d], 1);
    g_srcs[p] = g_inv[ei[e]];
}

// ---------------- HMMA tf32 GEMM v5: ldmatrix frags, 512 thr / 16 warps ------
// xlr[compact,512] = A @ W + biasC;  A = [h|h0] (K=128) or h (K=64 vs WsumT).
// B in smem n-major (Bt[n][k]) so ldmatrix.x4.b16 yields tf32 frags directly.
#define GEMM_SMEM (2 * 128 * PAD * 4)
#define GT 512

template<int KD>
__device__ __forceinline__ void gemm_body(int tsel, uint32_t* smg) {
    uint32_t* As = smg;               // [128 rows][PAD]  (row-major, k along row)
    uint32_t* Bs = smg + 128 * PAD;   // [128 n-rows][PAD] (n-major, k along row)
    int nact = g_nact[tsel];
    int ntile = (nact + 127) >> 7;
    int colB = blockIdx.x * 128;
    int tid = threadIdx.x, lane = tid & 31, wid = tid >> 5;
    int mwarp = wid >> 2, nwarp = wid & 3;      // 4M x 4N
    int group = lane >> 2, tig = lane & 3;
    const float* WT = (KD == 128) ? g_WpT : g_WsumT;
    constexpr int NCPY = (KD == 128) ? 8 : 4;   // float4 per thread (A stage)
    constexpr int SEGW = (KD == 128) ? 32 : 16; // floats per A stage segment
    constexpr int K4 = KD / 4;

    // B stage once per CTA: Bs[n][k] = WT[(colB+n)*KD + k]  (coalesced rows)
    for (int i = tid; i < 128 * K4; i += GT) {
        int n = i / K4, k4 = (i % K4) * 4;
        float4 v = *(const float4*)&WT[(size_t)(colB + n) * KD + k4];
        uint32_t* d = &Bs[n * PAD + k4];
        d[0] = __float_as_uint(v.x); d[1] = __float_as_uint(v.y);
        d[2] = __float_as_uint(v.z); d[3] = __float_as_uint(v.w);
    }

    float2 bia[4];
#pragma unroll
    for (int nf = 0; nf < 4; nf++)
        bia[nf] = *(const float2*)&g_biasC[colB + nwarp * 32 + nf * 8 + 2 * tig];

    // ldmatrix source addresses (k0-invariant part)
    uint32_t sbA, sbB;
    asm("{ .reg .u64 t; cvta.to.shared.u64 t, %1; cvt.u32.u64 %0, t; }" : "=r"(sbA) : "l"(As));
    asm("{ .reg .u64 t; cvta.to.shared.u64 t, %1; cvt.u32.u64 %0, t; }" : "=r"(sbB) : "l"(Bs));
    // A: lanes 0-15 -> rows (lane&15), k-lo; lanes 16-31 -> same rows, k+4
    uint32_t aad0 = sbA + (uint32_t)(((mwarp * 32 + (lane & 15)) * PAD + ((lane >> 4) << 2)) * 4);
    uint32_t aad1 = aad0 + 16 * PAD * 4;
    // B: lanes 0-7 rows n0..n0+7 k-lo; 8-15 same rows k-hi; 16-23 rows +8 k-lo; 24-31 rows +8 k-hi
    uint32_t bad0 = sbB + (uint32_t)(((nwarp * 32 + ((lane >> 4) << 3) + (lane & 7)) * PAD
                                      + (((lane >> 3) & 1) << 2)) * 4);
    uint32_t bad1 = bad0 + 16 * PAD * 4;

    // A stage mapping: row = tid&127, segment = tid>>7
    int m_st = tid & 127, seg = tid >> 7;
    float4 pf[NCPY];

    auto srcp = [&](int gr) -> const float4* {
        if (KD == 128) {
            const float* s = (seg >= 2) ? g_h0 : g_h;
            return (const float4*)&s[(size_t)gr * 64 + (seg & 1) * 32];
        } else {
            return (const float4*)&g_h[(size_t)gr * 64 + seg * 16];
        }
    };

    int tile = blockIdx.y;
    if (tile < ntile) {
        int r = (tile << 7) + m_st;
        const float4* sp = srcp((r < nact) ? g_order[r] : g_order[0]);
#pragma unroll
        for (int i = 0; i < NCPY; i++) pf[i] = sp[i];
    }

    for (; tile < ntile; tile += gridDim.y) {
        __syncthreads();                 // prev tile's As reads complete
        {
            float4* dst = (float4*)&As[m_st * PAD + seg * SEGW];
#pragma unroll
            for (int i = 0; i < NCPY; i++) dst[i] = pf[i];
        }
        __syncthreads();                 // As ready

        // prefetch NEXT tile's A rows
        int nxt = tile + gridDim.y;
        if (nxt < ntile) {
            int r = (nxt << 7) + m_st;
            const float4* sp = srcp((r < nact) ? g_order[r] : g_order[0]);
#pragma unroll
            for (int i = 0; i < NCPY; i++) pf[i] = sp[i];
        }

        float acc[2][4][4];
#pragma unroll
        for (int mf = 0; mf < 2; mf++)
#pragma unroll
            for (int nf = 0; nf < 4; nf++)
#pragma unroll
                for (int q = 0; q < 4; q++) acc[mf][nf][q] = 0.f;

#pragma unroll 4
        for (int k0 = 0; k0 < KD / 8; k0++) {
            uint32_t koff = (uint32_t)(k0 * 32);
            uint32_t a0[4], a1[4], b0[4], b1[4];
            LDSM4(a0, aad0 + koff);
            LDSM4(a1, aad1 + koff);
            LDSM4(b0, bad0 + koff);
            LDSM4(b1, bad1 + koff);
            const uint32_t* bb[4][2] = {{&b0[0], &b0[1]}, {&b0[2], &b0[3]},
                                        {&b1[0], &b1[1]}, {&b1[2], &b1[3]}};
#pragma unroll
            for (int mf = 0; mf < 2; mf++) {
                const uint32_t* aa = mf ? a1 : a0;
#pragma unroll
                for (int nf = 0; nf < 4; nf++) {
                    asm volatile(
                        "mma.sync.aligned.m16n8k8.row.col.f32.tf32.tf32.f32 "
                        "{%0,%1,%2,%3}, {%4,%5,%6,%7}, {%8,%9}, {%0,%1,%2,%3};"
                        : "+f"(acc[mf][nf][0]), "+f"(acc[mf][nf][1]),
                          "+f"(acc[mf][nf][2]), "+f"(acc[mf][nf][3])
                        : "r"(aa[0]), "r"(aa[1]), "r"(aa[2]), "r"(aa[3]),
                          "r"(*bb[nf][0]), "r"(*bb[nf][1]));
                }
            }
        }

        int row0 = tile << 7;
#pragma unroll
        for (int mf = 0; mf < 2; mf++) {
            int r0 = row0 + mwarp * 32 + mf * 16 + group;
#pragma unroll
            for (int nf = 0; nf < 4; nf++) {
                int c = colB + nwarp * 32 + nf * 8 + 2 * tig;
                if (r0 < nact) {
                    float2 v = make_float2(acc[mf][nf][0] + bia[nf].x,
                                           acc[mf][nf][1] + bia[nf].y);
                    *(float2*)&g_xlr[(size_t)r0 * XD + c] = v;
                }
                if (r0 + 8 < nact) {
                    float2 v = make_float2(acc[mf][nf][2] + bia[nf].x,
                                           acc[mf][nf][3] + bia[nf].y);
                    *(float2*)&g_xlr[(size_t)(r0 + 8) * XD + c] = v;
                }
            }
        }
    }
}

__global__ __launch_bounds__(GT, 1) void k_gemm_mma(int tsel, int kd) {
    extern __shared__ uint32_t smg[];
    if (kd == 128) gemm_body<128>(tsel, smg);
    else           gemm_body<64>(tsel, smg);
}

// ---------------- edge kernel: one warp per compact active dst ---------------
__global__ void k_edge(const float* __restrict__ att, int t) {
    int w = (blockIdx.x * blockDim.x + threadIdx.x) >> 5;
    int lane = threadIdx.x & 31;
    int na = g_nact[t];
    if (w >= na) return;
    int norig = g_order[w];

    int j0 = lane * 8;
    const float4 at0 = *(const float4*)&att[j0];
    const float4 at1 = *(const float4*)&att[j0 + 4];
    const float* xrp = &g_xlr[(size_t)w * XD + 256 + j0];
    const float4 xr0 = *(const float4*)xrp;
    const float4 xr1 = *(const float4*)(xrp + 4);

    float acc[8];
#pragma unroll
    for (int i = 0; i < 8; i++) acc[i] = 0.f;
    float den = 0.f;

    int beg = g_beg[norig];
    int end = g_cnt[norig];
    for (int e = beg; e < end; e++) {
        int cs = g_srcs[e];
        if (cs >= na) continue;            // src inactive at step t
        const float* xp = &g_xlr[(size_t)cs * XD + j0];
        const float4 x0 = *(const float4*)xp;
        const float4 x1 = *(const float4*)(xp + 4);
        float p, v;
        v = x0.x + xr0.x; v = v > 0.f ? v : 0.2f * v; p  = v * at0.x;
        v = x0.y + xr0.y; v = v > 0.f ? v : 0.2f * v; p += v * at0.y;
        v = x0.z + xr0.z; v = v > 0.f ? v : 0.2f * v; p += v * at0.z;
        v = x0.w + xr0.w; v = v > 0.f ? v : 0.2f * v; p += v * at0.w;
        v = x1.x + xr1.x; v = v > 0.f ? v : 0.2f * v; p += v * at1.x;
        v = x1.y + xr1.y; v = v > 0.f ? v : 0.2f * v; p += v * at1.y;
        v = x1.z + xr1.z; v = v > 0.f ? v : 0.2f * v; p += v * at1.z;
        v = x1.w + xr1.w; v = v > 0.f ? v : 0.2f * v; p += v * at1.w;
        p += __shfl_xor_sync(0xffffffffu, p, 1);
        p += __shfl_xor_sync(0xffffffffu, p, 2);
        p += __shfl_xor_sync(0xffffffffu, p, 4);
        float ex = __expf(p);              // softmax shift-invariant
        den += ex;
        acc[0] += ex * x0.x; acc[1] += ex * x0.y;
        acc[2] += ex * x0.z; acc[3] += ex * x0.w;
        acc[4] += ex * x1.x; acc[5] += ex * x1.y;
        acc[6] += ex * x1.z; acc[7] += ex * x1.w;
    }

    float rden = 1.f / fmaxf(den, 1e-16f);
    float vres[8];
#pragma unroll
    for (int i = 0; i < 8; i++) {
        float v = acc[i] * rden;
        v += __shfl_xor_sync(0xffffffffu, v, 8);
        v += __shfl_xor_sync(0xffffffffu, v, 16);
        vres[i] = v;
    }
    if (lane < 8) {
#pragma unroll
        for (int i = 0; i < 8; i++) {
            int c = lane * 8 + i;
            g_h[norig * 64 + c] = t32(tanhf(vres[i] + g_bias2[c]));
        }
    }
}

// ---------------- out = (h @ Wg + bg) * (current_state > 0) -----------------
__global__ void k_out(const float* __restrict__ Wg, const float* __restrict__ bg,
                      const int* __restrict__ cs, float* __restrict__ out) {
    __shared__ float Ws[64 * 32];
    __shared__ float hs[8][64];
    int tid = threadIdx.x;
    for (int i = tid; i < 64 * 32; i += 256) Ws[i] = Wg[i];
    for (int i = tid; i < 8 * 64; i += 256) {
        int r = blockIdx.x * 8 + (i >> 6);
        hs[i >> 6][i & 63] = (r < N_NODES) ? g_h[r * 64 + (i & 63)] : 0.f;
    }
    __syncthreads();
    int ty = tid >> 5;
    int c = tid & 31;
    int r = blockIdx.x * 8 + ty;
    if (r >= N_NODES) return;
    if (cs[r] <= 0) { out[r * 32 + c] = 0.f; return; }
    float s = bg[c];
#pragma unroll
    for (int k = 0; k < 64; k++) s += hs[ty][k] * Ws[k * 32 + c];
    out[r * 32 + c] = s;
}

// ---------------- launch -----------------------------------------------------
extern "C" void kernel_launch(void* const* d_in, const int* in_sizes, int n_in,
                              void* d_out, int out_size) {
    const float* feat  = (const float*)d_in[0];
    const float* W_in  = (const float*)d_in[1];
    const float* b_in  = (const float*)d_in[2];
    const float* Wl    = (const float*)d_in[3];
    const float* bl    = (const float*)d_in[4];
    const float* Wr    = (const float*)d_in[5];
    const float* br    = (const float*)d_in[6];
    const float* att   = (const float*)d_in[7];
    const float* bconv = (const float*)d_in[8];
    const float* Wg    = (const float*)d_in[9];
    const float* bg    = (const float*)d_in[10];
    const int*   ei    = (const int*)d_in[11];
    const int*   mask  = (const int*)d_in[12];
    const int*   cstat = (const int*)d_in[13];
    float* out = (float*)d_out;

    cudaFuncSetAttribute(k_gemm_mma, cudaFuncAttributeMaxDynamicSharedMemorySize, GEMM_SMEM);

    k_l0<<<L0_GRID, 256>>>(feat, W_in, b_in, Wl, Wr, bl, br, bconv, mask);   // 0
    k_count<<<(E_EDGES + 255) / 256, 256>>>(ei);                              // 1
    k_assign<<<196, 256>>>(mask);                                             // 2
    k_gemm_mma<<<dim3(4, 37), GT, GEMM_SMEM>>>(0, 64);                        // 3 <- ncu
    k_fill<<<(E_EDGES + 255) / 256, 256>>>(ei);                               // 4
    k_edge<<<(N_NODES * 32) / 256, 256>>>(att, 0);                            // 5
    k_gemm_mma<<<dim3(4, 37), GT, GEMM_SMEM>>>(1, 128);                       // 6
    k_edge<<<(N_NODES * 32) / 256, 256>>>(att, 1);                            // 7
    k_gemm_mma<<<dim3(4, 37), GT, GEMM_SMEM>>>(2, 128);                       // 8
    k_edge<<<(N_NODES * 32) / 256, 256>>>(att, 2);                            // 9
    k_out<<<(N_NODES + 7) / 8, 256>>>(Wg, bg, cstat, out);                    // 10
}